// round 11
// baseline (speedup 1.0000x reference)
#include <cuda_runtime.h>
#include <math.h>

// Problem dims
#define NB   16
#define TT   512
#define DD   512
#define NM   8
#define NH   8
#define DHD  64
#define OUTF 2048
#define CSIZE 8
#define SCAN_THREADS 1024

// ---------------------------------------------------------------------------
// Scratch (static __device__ — no allocations allowed)
// ---------------------------------------------------------------------------
__device__ __align__(16) float g_Wpack[4 * 16 * 8 * 512 * 4]; // [pp][kk][ks][col][4]
__device__ __align__(16) float g_O[NB][NM][DD];               // attention out exchange
__device__ __align__(16) float g_resid[NB][NM][DD];           // residual (pre-LN)
__device__ float g_part[NB][CSIZE][NM][2];                    // LN partial (sum, sumsq)
__device__ __align__(16) float g_KVy[NB * TT][2 * DD];        // precomputed K,V of y_t
__device__ __align__(16) float g_MS[NB * TT][DD];             // summaries

// ---------------------------------------------------------------------------
// f32x2 packed helpers
// ---------------------------------------------------------------------------
__device__ __forceinline__ void fma2(unsigned long long& d,
                                     unsigned long long a, unsigned long long b) {
    asm("fma.rn.f32x2 %0, %1, %2, %0;" : "+l"(d) : "l"(a), "l"(b));
}
__device__ __forceinline__ float2 u2f2(unsigned long long v) {
    float2 f; asm("mov.b64 {%0,%1}, %2;" : "=f"(f.x), "=f"(f.y) : "l"(v)); return f;
}

// ---------------------------------------------------------------------------
// Weight repack: g_Wpack[(((pp*16+kk)*8+ks)*512+col)*4+e] = W[col][ks*64+kk*4+e]
// ---------------------------------------------------------------------------
__global__ void repack_kernel(const float* __restrict__ Wqkv,
                              const float* __restrict__ Wo) {
    int idx = blockIdx.x * 256 + threadIdx.x;   // 0 .. 2^20-1
    int e   = idx & 3;
    int col = (idx >> 2) & 511;
    int ks  = (idx >> 11) & 7;
    int kk  = (idx >> 14) & 15;
    int pp  = idx >> 18;
    int k   = ks * 64 + kk * 4 + e;
    float v = (pp < 3) ? Wqkv[((size_t)(pp * 512 + col)) * 512 + k]
                       : Wo[(size_t)col * 512 + k];
    g_Wpack[idx] = v;
}

__global__ void dummy_kernel() {}

// ---------------------------------------------------------------------------
// Generic GEMM-NT: C = act(bias + A @ W^T), K=512
// ---------------------------------------------------------------------------
template <bool GATHER, bool RELU>
__global__ __launch_bounds__(256) void gemm_nt(
    const float* __restrict__ A, const int* __restrict__ ids,
    const float* __restrict__ emb,
    const float* __restrict__ W, const float* __restrict__ bias,
    float* __restrict__ C, int M, int N)
{
    __shared__ float As[16][132];
    __shared__ float Bs[16][132];

    const int tid = threadIdx.x;
    const int ty = tid >> 4;
    const int tx = tid & 15;
    const int m0 = blockIdx.y * 128;
    const int n0 = blockIdx.x * 128;

    float acc[8][8];
#pragma unroll
    for (int i = 0; i < 8; i++)
#pragma unroll
        for (int j = 0; j < 8; j++) acc[i][j] = 0.f;

    for (int kt = 0; kt < 512; kt += 16) {
#pragma unroll
        for (int s = 0; s < 2; s++) {
            int slot = tid + s * 256;
            int r = slot >> 2;
            int q = (slot & 3) * 4;
            float4 v, w;
            if (GATHER) {
                int id = ids[m0 + r];
                if (id != 0)
                    v = *(const float4*)(emb + (size_t)id * 512 + kt + q);
                else
                    v = make_float4(0.f, 0.f, 0.f, 0.f);
            } else {
                v = *(const float4*)(A + (size_t)(m0 + r) * 512 + kt + q);
            }
            w = *(const float4*)(W + (size_t)(n0 + r) * 512 + kt + q);
            As[q + 0][r] = v.x; As[q + 1][r] = v.y;
            As[q + 2][r] = v.z; As[q + 3][r] = v.w;
            Bs[q + 0][r] = w.x; Bs[q + 1][r] = w.y;
            Bs[q + 2][r] = w.z; Bs[q + 3][r] = w.w;
        }
        __syncthreads();
#pragma unroll
        for (int kk = 0; kk < 16; kk++) {
            const float4 a0 = *(const float4*)&As[kk][ty * 8];
            const float4 a1 = *(const float4*)&As[kk][ty * 8 + 4];
            const float4 b0 = *(const float4*)&Bs[kk][tx * 8];
            const float4 b1 = *(const float4*)&Bs[kk][tx * 8 + 4];
            float ar[8] = {a0.x, a0.y, a0.z, a0.w, a1.x, a1.y, a1.z, a1.w};
            float br[8] = {b0.x, b0.y, b0.z, b0.w, b1.x, b1.y, b1.z, b1.w};
#pragma unroll
            for (int i = 0; i < 8; i++)
#pragma unroll
                for (int j = 0; j < 8; j++)
                    acc[i][j] = fmaf(ar[i], br[j], acc[i][j]);
        }
        __syncthreads();
    }

#pragma unroll
    for (int i = 0; i < 8; i++) {
        int m = m0 + ty * 8 + i;
#pragma unroll
        for (int j = 0; j < 8; j++) {
            int n = n0 + tx * 8 + j;
            float v = acc[i][j] + bias[n];
            if (RELU) v = fmaxf(v, 0.f);
            C[(size_t)m * N + n] = v;
        }
    }
}

// ---------------------------------------------------------------------------
// Scan kernel: cluster of 8 CTAs per batch, 1024 threads per CTA (32 warps).
// CTA `rank` owns columns [64r, 64r+64) == head r.
// Thread layout (projections): ih = tid>>9 (row half), ks = (tid>>6)&7,
// cl = tid&63. X/O reads are warp broadcasts; weights coalesced 512B/warp.
// ---------------------------------------------------------------------------
struct SmemScan {
    float Xs[NM][DD];            // normalized state
    float Os[NM][DD];            // full attention output
    float part[3 * NM * 8 * 64]; // k-split partials [p][i][ks][cl]
    float Qs[NM][68];
    float Ks2[NM + 1][68];
    float Vs2[NM + 1][68];
    float Sc[NM][12];
    float wpart[NM][2][2];
    float muinv[NM][2];
    float bq_s[64], bk_s[64], bv_s[64], bo_s[64];
};

__global__ __launch_bounds__(SCAN_THREADS, 1) __cluster_dims__(CSIZE, 1, 1)
void scan_kernel(const float* __restrict__ mem_init,
                 const float* __restrict__ bqkv,
                 const float* __restrict__ bo,
                 const float* __restrict__ lng, const float* __restrict__ lnb)
{
    extern __shared__ char smem_raw[];
    SmemScan* sm = (SmemScan*)smem_raw;

    const int tid = threadIdx.x;
    const int rank = blockIdx.x;          // cluster cta rank == head
    const int b = blockIdx.y;             // batch
    const int ih = tid >> 9;              // row half (0/1)
    const int ks = (tid >> 6) & 7;        // k-slice
    const int cl = tid & 63;              // column within head
    const int col = rank * 64 + cl;       // global column
    const int i0 = ih * 4;                // first owned row
    const ulonglong2* Wp = (const ulonglong2*)g_Wpack;

    const float4* Xs4 = (const float4*)sm->Xs;
    const float4* Os4 = (const float4*)sm->Os;
    float* Xsf = (float*)sm->Xs;

    // LN constants for the rebuild (v = tid covers 1024 float4s of 8x512)
    const float4 lngv = ((const float4*)lng)[tid & 127];
    const float4 lnbv = ((const float4*)lnb)[tid & 127];

    // Stage biases for own columns + init Xs = mem_init
    if (tid < 64) {
        sm->bq_s[tid] = bqkv[rank * 64 + tid];
        sm->bk_s[tid] = bqkv[DD + rank * 64 + tid];
        sm->bv_s[tid] = bqkv[2 * DD + rank * 64 + tid];
        sm->bo_s[tid] = bo[rank * 64 + tid];
    }
    {
        const float4* src = (const float4*)mem_init;
        ((float4*)sm->Xs)[tid] = src[tid];
    }
    __syncthreads();

    for (int t = 0; t < TT; t++) {
        // --- prefetch y_t's k,v head-slice into row 8 ---------------------------
        if (tid < 32) {
            const float4* kvy = (const float4*)&g_KVy[b * TT + t][0];
            int q = tid & 15;
            if (tid < 16) {
                float4 v = kvy[rank * 16 + q];
                *(float4*)&sm->Ks2[NM][q * 4] = v;
            } else {
                float4 v = kvy[128 + rank * 16 + q];
                *(float4*)&sm->Vs2[NM][q * 4] = v;
            }
        }

        // --- phase 1: fused Q/K/V partial projections (4 rows per thread) -------
        {
            unsigned long long acc[3][4];
#pragma unroll
            for (int p = 0; p < 3; p++)
#pragma unroll
                for (int ii = 0; ii < 4; ii++) acc[p][ii] = 0ull;

#pragma unroll 2
            for (int kk = 0; kk < 16; kk++) {
                const int wi = (kk * 8 + ks) * 512 + col;
                ulonglong2 wq = Wp[wi];
                ulonglong2 wk = Wp[wi + 65536];
                ulonglong2 wv = Wp[wi + 131072];
                const int xc = ks * 16 + kk;          // float4 chunk in row
#pragma unroll
                for (int ii = 0; ii < 4; ii++) {
                    ulonglong2 x = *(const ulonglong2*)(Xs4 + (i0 + ii) * 128 + xc);
                    fma2(acc[0][ii], x.x, wq.x); fma2(acc[0][ii], x.y, wq.y);
                    fma2(acc[1][ii], x.x, wk.x); fma2(acc[1][ii], x.y, wk.y);
                    fma2(acc[2][ii], x.x, wv.x); fma2(acc[2][ii], x.y, wv.y);
                }
            }
            // store partials [p][i][ks][cl] (cl-contiguous -> conflict-free)
#pragma unroll
            for (int p = 0; p < 3; p++)
#pragma unroll
                for (int ii = 0; ii < 4; ii++) {
                    float2 f = u2f2(acc[p][ii]);
                    sm->part[((p * NM + i0 + ii) * 8 + ks) * 64 + cl] = f.x + f.y;
                }
        }
        __syncthreads();

        // --- k-reduction: 1536 outputs over 1024 threads --------------------------
        for (int idx = tid; idx < 3 * NM * 64; idx += SCAN_THREADS) {
            int p = idx >> 9;
            int i = (idx >> 6) & 7;
            int c = idx & 63;
            const float* pp = &sm->part[(p * NM + i) * 8 * 64 + c];
            float s = 0.f;
#pragma unroll
            for (int r2 = 0; r2 < 8; r2++) s += pp[r2 * 64];
            if (p == 0)      sm->Qs[i][c]  = s + sm->bq_s[c];
            else if (p == 1) sm->Ks2[i][c] = s + sm->bk_s[c];
            else             sm->Vs2[i][c] = s + sm->bv_s[c];
        }
        __syncthreads();

        // --- scores for own head: s[i][j] = q_i . k_j / 8 ------------------------
        if (tid < NM * (NM + 1)) {
            int i = tid / (NM + 1);
            int j = tid - i * (NM + 1);
            const float* q = sm->Qs[i];
            const float* kr = sm->Ks2[j];
            float s = 0.f;
#pragma unroll
            for (int d = 0; d < DHD; d += 4) {
                float4 a = *(const float4*)(q + d);
                float4 c = *(const float4*)(kr + d);
                s = fmaf(a.x, c.x, fmaf(a.y, c.y,
                     fmaf(a.z, c.z, fmaf(a.w, c.w, s))));
            }
            sm->Sc[i][j] = s * 0.125f;
        }
        __syncthreads();

        // --- softmax over 9 entries (8 threads) ----------------------------------
        if (tid < NM) {
            float mx = -1e30f;
#pragma unroll
            for (int j = 0; j < NM + 1; j++) mx = fmaxf(mx, sm->Sc[tid][j]);
            float e[NM + 1];
            float sum = 0.f;
#pragma unroll
            for (int j = 0; j < NM + 1; j++) {
                e[j] = expf(sm->Sc[tid][j] - mx);
                sum += e[j];
            }
            float inv = 1.f / sum;
#pragma unroll
            for (int j = 0; j < NM + 1; j++) sm->Sc[tid][j] = e[j] * inv;
        }
        __syncthreads();

        // --- O slice = A @ V (own head), write to exchange buffer ----------------
        if (tid < 512) {
            int i = tid >> 6, c = tid & 63;
            float o = 0.f;
#pragma unroll
            for (int j = 0; j < NM + 1; j++)
                o = fmaf(sm->Sc[i][j], sm->Vs2[j][c], o);
            g_O[b][i][rank * 64 + c] = o;
        }

        // --- cluster barrier #1 (O exchange); prefetch out-proj weights ----------
        ulonglong2 wo[16];
        asm volatile("barrier.cluster.arrive.aligned;" ::: "memory");
#pragma unroll
        for (int kk = 0; kk < 16; kk++)
            wo[kk] = Wp[196608 + (kk * 8 + ks) * 512 + col];
        asm volatile("barrier.cluster.wait.aligned;" ::: "memory");

        // --- load full O into smem -------------------------------------------------
        {
            const float4* osrc = (const float4*)&g_O[b][0][0];
            ((float4*)sm->Os)[tid] = osrc[tid];
        }
        __syncthreads();

        // --- out-projection partials (4 rows per thread, weights in regs) --------
        {
            unsigned long long acc[4];
#pragma unroll
            for (int ii = 0; ii < 4; ii++) acc[ii] = 0ull;
#pragma unroll 2
            for (int kk = 0; kk < 16; kk++) {
                const int xc = ks * 16 + kk;
#pragma unroll
                for (int ii = 0; ii < 4; ii++) {
                    ulonglong2 x = *(const ulonglong2*)(Os4 + (i0 + ii) * 128 + xc);
                    fma2(acc[ii], x.x, wo[kk].x);
                    fma2(acc[ii], x.y, wo[kk].y);
                }
            }
#pragma unroll
            for (int ii = 0; ii < 4; ii++) {
                float2 f = u2f2(acc[ii]);
                sm->part[((i0 + ii) * 8 + ks) * 64 + cl] = f.x + f.y;
            }
        }
        __syncthreads();

        // --- reduce out-proj, residual, LN partial stats (tid < 512) ---------------
        if (tid < 512) {
            int i = tid >> 6, c = tid & 63;
            const float* pp = &sm->part[i * 8 * 64 + c];
            float s = 0.f;
#pragma unroll
            for (int r2 = 0; r2 < 8; r2++) s += pp[r2 * 64];
            float r = Xsf[i * DD + rank * 64 + c] + s + sm->bo_s[c];
            g_resid[b][i][rank * 64 + c] = r;

            float s1 = r, s2 = r * r;
#pragma unroll
            for (int off = 16; off; off >>= 1) {
                s1 += __shfl_xor_sync(0xffffffffu, s1, off);
                s2 += __shfl_xor_sync(0xffffffffu, s2, off);
            }
            if ((tid & 31) == 0) {
                int half = (tid >> 5) & 1;
                sm->wpart[i][half][0] = s1;
                sm->wpart[i][half][1] = s2;
            }
        }
        __syncthreads();
        if (tid < NM) {
            g_part[b][rank][tid][0] = sm->wpart[tid][0][0] + sm->wpart[tid][1][0];
            g_part[b][rank][tid][1] = sm->wpart[tid][0][1] + sm->wpart[tid][1][1];
        }
        asm volatile("barrier.cluster.arrive.aligned;" ::: "memory");
        asm volatile("barrier.cluster.wait.aligned;" ::: "memory");   // #2

        // --- LN finalize (redundant per CTA), rebuild full Xs ----------------------
        if (tid < NM) {
            float S = 0.f, SS = 0.f;
#pragma unroll
            for (int r2 = 0; r2 < CSIZE; r2++) {
                S  += g_part[b][r2][tid][0];
                SS += g_part[b][r2][tid][1];
            }
            float mu = S * (1.f / 512.f);
            float var = SS * (1.f / 512.f) - mu * mu;
            sm->muinv[tid][0] = mu;
            sm->muinv[tid][1] = rsqrtf(var + 1e-5f);
        }
        __syncthreads();
        {
            const float4* rsrc = (const float4*)&g_resid[b][0][0];
            int i = tid >> 7;
            float mu = sm->muinv[i][0], inv = sm->muinv[i][1];
            float4 r = rsrc[tid];
            float4 y;
            y.x = (r.x - mu) * inv * lngv.x + lnbv.x;
            y.y = (r.y - mu) * inv * lngv.y + lnbv.y;
            y.z = (r.z - mu) * inv * lngv.z + lnbv.z;
            y.w = (r.w - mu) * inv * lngv.w + lnbv.w;
            ((float4*)sm->Xs)[tid] = y;
        }
        __syncthreads();

        // --- summary (own 64 columns) ------------------------------------------------
        if (tid < 64) {
            int c = rank * 64 + tid;
            float s = 0.f;
#pragma unroll
            for (int i = 0; i < NM; i++) s += Xsf[i * DD + c];
            g_MS[b * TT + t][c] = s * 0.125f;
        }
        __syncthreads();
    }
}

// ---------------------------------------------------------------------------
// Launch
// ---------------------------------------------------------------------------
extern "C" void kernel_launch(void* const* d_in, const int* in_sizes, int n_in,
                              void* d_out, int out_size) {
    const int*   ids        = (const int*)d_in[0];
    const float* embedding  = (const float*)d_in[1];
    const float* mem_init   = (const float*)d_in[2];
    const float* in_proj_w  = (const float*)d_in[3];
    const float* in_proj_b  = (const float*)d_in[4];
    const float* out_proj_w = (const float*)d_in[5];
    const float* out_proj_b = (const float*)d_in[6];
    const float* ln_g       = (const float*)d_in[7];
    const float* ln_b       = (const float*)d_in[8];
    const float* proj_w     = (const float*)d_in[9];
    const float* proj_b     = (const float*)d_in[10];
    float* out = (float*)d_out;

    void *pKVy = nullptr, *pMS = nullptr;
    cudaGetSymbolAddress(&pKVy, g_KVy);
    cudaGetSymbolAddress(&pMS, g_MS);

    cudaFuncSetAttribute(scan_kernel,
                         cudaFuncAttributeMaxDynamicSharedMemorySize,
                         (int)sizeof(SmemScan));

    // 1) repack weights                                       (launch 0)
    repack_kernel<<<4096, 256>>>(in_proj_w, out_proj_w);

    // 2) precompute K,V projections of all tokens             (launch 1)
    {
        dim3 grid((2 * DD) / 128, (NB * TT) / 128);
        gemm_nt<true, false><<<grid, 256>>>(
            nullptr, ids, embedding,
            in_proj_w + (size_t)DD * DD, in_proj_b + DD,
            (float*)pKVy, NB * TT, 2 * DD);
    }

    // padding so ncu lands on the scan (profiled index = 3)   (launch 2)
    dummy_kernel<<<1, 32>>>();

    // 3) sequential scan: 16 clusters x 8 CTAs                (launch 3)
    scan_kernel<<<dim3(CSIZE, NB), SCAN_THREADS, sizeof(SmemScan)>>>(
        mem_init, in_proj_b, out_proj_b, ln_g, ln_b);

    // 4) final projection: relu(MS @ proj_w^T + proj_b)       (launch 4)
    {
        dim3 grid(OUTF / 128, (NB * TT) / 128);
        gemm_nt<false, true><<<grid, 256>>>(
            (const float*)pMS, nullptr, nullptr,
            proj_w, proj_b, out, NB * TT, OUTF);
    }
}

// round 12
// speedup vs baseline: 1.2141x; 1.2141x over previous
#include <cuda_runtime.h>
#include <math.h>

// Problem dims
#define NB   16
#define TT   512
#define DD   512
#define NM   8
#define NH   8
#define DHD  64
#define OUTF 2048
#define CSIZE 8
#define SCAN_THREADS 512

// ---------------------------------------------------------------------------
// Scratch (static __device__ — no allocations allowed)
// ---------------------------------------------------------------------------
__device__ __align__(16) float g_Wpack[4 * 16 * 8 * 512 * 4]; // [pp][kk][ks][col][4]
__device__ __align__(16) float g_O[NB][NM][DD];               // attention out exchange
__device__ __align__(16) float g_resid[NB][NM][DD];           // residual (pre-LN)
__device__ __align__(16) float g_part[NB][CSIZE][NM][2];      // LN partial (sum, sumsq)
__device__ __align__(16) float g_KVy[NB * TT][2 * DD];        // precomputed K,V of y_t
__device__ __align__(16) float g_MS[NB * TT][DD];             // summaries

// ---------------------------------------------------------------------------
// f32x2 packed helpers
// ---------------------------------------------------------------------------
__device__ __forceinline__ void fma2(unsigned long long& d,
                                     unsigned long long a, unsigned long long b) {
    asm("fma.rn.f32x2 %0, %1, %2, %0;" : "+l"(d) : "l"(a), "l"(b));
}
__device__ __forceinline__ float2 u2f2(unsigned long long v) {
    float2 f; asm("mov.b64 {%0,%1}, %2;" : "=f"(f.x), "=f"(f.y) : "l"(v)); return f;
}

// ---------------------------------------------------------------------------
// Weight repack: g_Wpack[(((pp*16+kk)*8+ks)*512+col)*4+e] = W[col][ks*64+kk*4+e]
// ---------------------------------------------------------------------------
__global__ void repack_kernel(const float* __restrict__ Wqkv,
                              const float* __restrict__ Wo) {
    int idx = blockIdx.x * 256 + threadIdx.x;   // 0 .. 2^20-1
    int e   = idx & 3;
    int col = (idx >> 2) & 511;
    int ks  = (idx >> 11) & 7;
    int kk  = (idx >> 14) & 15;
    int pp  = idx >> 18;
    int k   = ks * 64 + kk * 4 + e;
    float v = (pp < 3) ? Wqkv[((size_t)(pp * 512 + col)) * 512 + k]
                       : Wo[(size_t)col * 512 + k];
    g_Wpack[idx] = v;
}

__global__ void dummy_kernel() {}

// ---------------------------------------------------------------------------
// Generic GEMM-NT: C = act(bias + A @ W^T), K=512
// ---------------------------------------------------------------------------
template <bool GATHER, bool RELU>
__global__ __launch_bounds__(256) void gemm_nt(
    const float* __restrict__ A, const int* __restrict__ ids,
    const float* __restrict__ emb,
    const float* __restrict__ W, const float* __restrict__ bias,
    float* __restrict__ C, int M, int N)
{
    __shared__ float As[16][132];
    __shared__ float Bs[16][132];

    const int tid = threadIdx.x;
    const int ty = tid >> 4;
    const int tx = tid & 15;
    const int m0 = blockIdx.y * 128;
    const int n0 = blockIdx.x * 128;

    float acc[8][8];
#pragma unroll
    for (int i = 0; i < 8; i++)
#pragma unroll
        for (int j = 0; j < 8; j++) acc[i][j] = 0.f;

    for (int kt = 0; kt < 512; kt += 16) {
#pragma unroll
        for (int s = 0; s < 2; s++) {
            int slot = tid + s * 256;
            int r = slot >> 2;
            int q = (slot & 3) * 4;
            float4 v, w;
            if (GATHER) {
                int id = ids[m0 + r];
                if (id != 0)
                    v = *(const float4*)(emb + (size_t)id * 512 + kt + q);
                else
                    v = make_float4(0.f, 0.f, 0.f, 0.f);
            } else {
                v = *(const float4*)(A + (size_t)(m0 + r) * 512 + kt + q);
            }
            w = *(const float4*)(W + (size_t)(n0 + r) * 512 + kt + q);
            As[q + 0][r] = v.x; As[q + 1][r] = v.y;
            As[q + 2][r] = v.z; As[q + 3][r] = v.w;
            Bs[q + 0][r] = w.x; Bs[q + 1][r] = w.y;
            Bs[q + 2][r] = w.z; Bs[q + 3][r] = w.w;
        }
        __syncthreads();
#pragma unroll
        for (int kk = 0; kk < 16; kk++) {
            const float4 a0 = *(const float4*)&As[kk][ty * 8];
            const float4 a1 = *(const float4*)&As[kk][ty * 8 + 4];
            const float4 b0 = *(const float4*)&Bs[kk][tx * 8];
            const float4 b1 = *(const float4*)&Bs[kk][tx * 8 + 4];
            float ar[8] = {a0.x, a0.y, a0.z, a0.w, a1.x, a1.y, a1.z, a1.w};
            float br[8] = {b0.x, b0.y, b0.z, b0.w, b1.x, b1.y, b1.z, b1.w};
#pragma unroll
            for (int i = 0; i < 8; i++)
#pragma unroll
                for (int j = 0; j < 8; j++)
                    acc[i][j] = fmaf(ar[i], br[j], acc[i][j]);
        }
        __syncthreads();
    }

#pragma unroll
    for (int i = 0; i < 8; i++) {
        int m = m0 + ty * 8 + i;
#pragma unroll
        for (int j = 0; j < 8; j++) {
            int n = n0 + tx * 8 + j;
            float v = acc[i][j] + bias[n];
            if (RELU) v = fmaxf(v, 0.f);
            C[(size_t)m * N + n] = v;
        }
    }
}

// ---------------------------------------------------------------------------
// Scan kernel: cluster of 8 CTAs per batch, 512 threads per CTA (16 warps).
// CTA `rank` owns columns [64r, 64r+64) == head r. Attention fully local.
// Thread layout (projections): ks = tid>>6, cl = tid&63.
// ---------------------------------------------------------------------------
struct SmemScan {
    float Xs[NM][DD];            // normalized state
    float Os[NM][DD];            // full attention output
    float part[3 * NM * 8 * 64]; // k-split partials [p][i][ks][cl]
    float Qs[NM][68];
    float Ks2[NM + 1][68];
    float Vs2[NM + 1][68];
    float Sc[NM][12];
    float wpart[NM][2][2];
};

__global__ __launch_bounds__(SCAN_THREADS, 1) __cluster_dims__(CSIZE, 1, 1)
void scan_kernel(const float* __restrict__ mem_init,
                 const float* __restrict__ bqkv,
                 const float* __restrict__ bo,
                 const float* __restrict__ lng, const float* __restrict__ lnb)
{
    extern __shared__ char smem_raw[];
    SmemScan* sm = (SmemScan*)smem_raw;

    const int tid = threadIdx.x;
    const int rank = blockIdx.x;          // cluster cta rank == head
    const int b = blockIdx.y;             // batch
    const int ks = tid >> 6;              // k-slice
    const int cl = tid & 63;              // column within head
    const int col = rank * 64 + cl;       // global column
    const ulonglong2* Wp = (const ulonglong2*)g_Wpack;

    const float4* Xs4 = (const float4*)sm->Xs;
    const float4* Os4 = (const float4*)sm->Os;
    float* Xsf = (float*)sm->Xs;

    // Hoisted per-thread constants
    const float bq2 = bqkv[col];
    const float bk2 = bqkv[DD + col];
    const float bv2 = bqkv[2 * DD + col];
    const float bo2 = bo[col];
    const float4 lng0 = ((const float4*)lng)[tid & 127];
    const float4 lnb0 = ((const float4*)lnb)[tid & 127];
    const float4 lng1 = ((const float4*)lng)[(tid + 512) & 127];
    const float4 lnb1 = ((const float4*)lnb)[(tid + 512) & 127];

    // Init Xs = mem_init (M0 broadcast)
    {
        const float4* src = (const float4*)mem_init;
        float4* xd = (float4*)sm->Xs;
        xd[tid] = src[tid];
        xd[tid + 512] = src[tid + 512];
    }
    __syncthreads();

    for (int t = 0; t < TT; t++) {
        // --- prefetch y_t's k,v head-slice into row 8 ---------------------------
        if (tid < 32) {
            const float4* kvy = (const float4*)&g_KVy[b * TT + t][0];
            int q = tid & 15;
            if (tid < 16) {
                float4 v = kvy[rank * 16 + q];
                *(float4*)&sm->Ks2[NM][q * 4] = v;
            } else {
                float4 v = kvy[128 + rank * 16 + q];
                *(float4*)&sm->Vs2[NM][q * 4] = v;
            }
        }

        // --- phase 1: fused Q/K/V partial projections (broadcast X reads) -------
        {
            unsigned long long acc[3][NM];
#pragma unroll
            for (int p = 0; p < 3; p++)
#pragma unroll
                for (int i = 0; i < NM; i++) acc[p][i] = 0ull;

#pragma unroll 4
            for (int kk = 0; kk < 16; kk++) {
                const int wi = (kk * 8 + ks) * 512 + col;
                ulonglong2 wq = Wp[wi];
                ulonglong2 wk = Wp[wi + 65536];
                ulonglong2 wv = Wp[wi + 131072];
                const int xc = ks * 16 + kk;          // float4 chunk in row
#pragma unroll
                for (int i = 0; i < NM; i++) {
                    ulonglong2 x = *(const ulonglong2*)(Xs4 + i * 128 + xc);
                    fma2(acc[0][i], x.x, wq.x); fma2(acc[0][i], x.y, wq.y);
                    fma2(acc[1][i], x.x, wk.x); fma2(acc[1][i], x.y, wk.y);
                    fma2(acc[2][i], x.x, wv.x); fma2(acc[2][i], x.y, wv.y);
                }
            }
            // store partials [p][i][ks][cl] (cl-contiguous -> conflict-free)
#pragma unroll
            for (int p = 0; p < 3; p++)
#pragma unroll
                for (int i = 0; i < NM; i++) {
                    float2 f = u2f2(acc[p][i]);
                    sm->part[((p * NM + i) * 8 + ks) * 64 + cl] = f.x + f.y;
                }
        }
        __syncthreads();

        // --- k-reduction: (i = tid>>6, c = tid&63), 3 outputs each ---------------
        {
            int i = ks, c = cl;
#pragma unroll
            for (int p = 0; p < 3; p++) {
                const float* pp = &sm->part[(p * NM + i) * 8 * 64 + c];
                float s = 0.f;
#pragma unroll
                for (int r2 = 0; r2 < 8; r2++) s += pp[r2 * 64];
                if (p == 0)      sm->Qs[i][c]  = s + bq2;
                else if (p == 1) sm->Ks2[i][c] = s + bk2;
                else             sm->Vs2[i][c] = s + bv2;
            }
        }
        __syncthreads();

        // --- fused scores + softmax: warp i handles query row i ------------------
        {
            int w = tid >> 5, lane = tid & 31;
            if (w < NM) {
                int jj = lane < 9 ? lane : 8;
                const float* q = sm->Qs[w];
                const float* kr = sm->Ks2[jj];
                float s = 0.f;
#pragma unroll
                for (int d = 0; d < DHD; d += 4) {
                    float4 a = *(const float4*)(q + d);
                    float4 c = *(const float4*)(kr + d);
                    s = fmaf(a.x, c.x, fmaf(a.y, c.y,
                         fmaf(a.z, c.z, fmaf(a.w, c.w, s))));
                }
                s = (lane < 9) ? s * 0.125f : -1e30f;
                float mx = s;
#pragma unroll
                for (int off = 16; off; off >>= 1)
                    mx = fmaxf(mx, __shfl_xor_sync(0xffffffffu, mx, off));
                float e = expf(s - mx);
                float sum = e;
#pragma unroll
                for (int off = 16; off; off >>= 1)
                    sum += __shfl_xor_sync(0xffffffffu, sum, off);
                if (lane < 9) sm->Sc[w][lane] = e / sum;
            }
        }
        __syncthreads();

        // --- O slice = A @ V (own head), write to exchange buffer ----------------
        {
            int i = ks, c = cl;
            float o = 0.f;
#pragma unroll
            for (int j = 0; j < NM + 1; j++)
                o = fmaf(sm->Sc[i][j], sm->Vs2[j][c], o);
            g_O[b][i][rank * 64 + c] = o;
        }

        // --- cluster barrier #1 (O exchange); prefetch out-proj weights ----------
        ulonglong2 wo[16];
        asm volatile("barrier.cluster.arrive.aligned;" ::: "memory");
#pragma unroll
        for (int kk = 0; kk < 16; kk++)
            wo[kk] = Wp[196608 + (kk * 8 + ks) * 512 + col];
        asm volatile("barrier.cluster.wait.aligned;" ::: "memory");

        // --- load full O into smem ------------------------------------------------
        {
            const float4* osrc = (const float4*)&g_O[b][0][0];
            float4* od = (float4*)sm->Os;
            od[tid] = osrc[tid];
            od[tid + 512] = osrc[tid + 512];
        }
        __syncthreads();

        // --- out-projection partials (broadcast O reads, weights in regs) --------
        {
            unsigned long long acc[NM];
#pragma unroll
            for (int i = 0; i < NM; i++) acc[i] = 0ull;
#pragma unroll 4
            for (int kk = 0; kk < 16; kk++) {
                const int xc = ks * 16 + kk;
#pragma unroll
                for (int i = 0; i < NM; i++) {
                    ulonglong2 x = *(const ulonglong2*)(Os4 + i * 128 + xc);
                    fma2(acc[i], x.x, wo[kk].x);
                    fma2(acc[i], x.y, wo[kk].y);
                }
            }
#pragma unroll
            for (int i = 0; i < NM; i++) {
                float2 f = u2f2(acc[i]);
                sm->part[(i * 8 + ks) * 64 + cl] = f.x + f.y;
            }
        }
        __syncthreads();

        // --- reduce out-proj, residual, LN partial stats ---------------------------
        {
            int i = ks, c = cl;
            const float* pp = &sm->part[i * 8 * 64 + c];
            float s = 0.f;
#pragma unroll
            for (int r2 = 0; r2 < 8; r2++) s += pp[r2 * 64];
            float r = Xsf[i * DD + col] + s + bo2;
            g_resid[b][i][col] = r;

            float s1 = r, s2 = r * r;
#pragma unroll
            for (int off = 16; off; off >>= 1) {
                s1 += __shfl_xor_sync(0xffffffffu, s1, off);
                s2 += __shfl_xor_sync(0xffffffffu, s2, off);
            }
            if ((tid & 31) == 0) {
                int half = (tid >> 5) & 1;
                sm->wpart[i][half][0] = s1;
                sm->wpart[i][half][1] = s2;
            }
        }
        __syncthreads();
        if (tid < NM) {
            float2 gp;
            gp.x = sm->wpart[tid][0][0] + sm->wpart[tid][1][0];
            gp.y = sm->wpart[tid][0][1] + sm->wpart[tid][1][1];
            *(float2*)&g_part[b][rank][tid][0] = gp;
        }
        asm volatile("barrier.cluster.arrive.aligned;" ::: "memory");
        asm volatile("barrier.cluster.wait.aligned;" ::: "memory");   // #2

        // --- LN finalize per-warp (shuffle stats), rebuild full Xs -----------------
        {
            int lane = tid & 31;
            int w = tid >> 5;
            int rowA = w >> 2;          // row of v = tid
            int rowB = 4 + (w >> 2);    // row of v = tid + 512
            int lr = lane & 7;
            int row = ((lane >> 3) & 1) ? rowB : rowA;
            float2 p = *(const float2*)&g_part[b][lr][row][0];
            float S = p.x, SS = p.y;
#pragma unroll
            for (int off = 1; off < 8; off <<= 1) {
                S  += __shfl_xor_sync(0xffffffffu, S, off);
                SS += __shfl_xor_sync(0xffffffffu, SS, off);
            }
            float mu = S * (1.f / 512.f);
            float var = SS * (1.f / 512.f) - mu * mu;
            float inv = rsqrtf(var + 1e-5f);
            float muA = __shfl_sync(0xffffffffu, mu, 0);
            float invA = __shfl_sync(0xffffffffu, inv, 0);
            float muB = __shfl_sync(0xffffffffu, mu, 8);
            float invB = __shfl_sync(0xffffffffu, inv, 8);

            const float4* rsrc = (const float4*)&g_resid[b][0][0];
            float4* xd = (float4*)sm->Xs;
            {
                float4 r = rsrc[tid];
                float4 y;
                y.x = (r.x - muA) * invA * lng0.x + lnb0.x;
                y.y = (r.y - muA) * invA * lng0.y + lnb0.y;
                y.z = (r.z - muA) * invA * lng0.z + lnb0.z;
                y.w = (r.w - muA) * invA * lng0.w + lnb0.w;
                xd[tid] = y;
            }
            {
                float4 r = rsrc[tid + 512];
                float4 y;
                y.x = (r.x - muB) * invB * lng1.x + lnb1.x;
                y.y = (r.y - muB) * invB * lng1.y + lnb1.y;
                y.z = (r.z - muB) * invB * lng1.z + lnb1.z;
                y.w = (r.w - muB) * invB * lng1.w + lnb1.w;
                xd[tid + 512] = y;
            }
        }
        __syncthreads();

        // --- summary (own 64 columns); no trailing sync needed ---------------------
        if (tid < 64) {
            int c = rank * 64 + tid;
            float s = 0.f;
#pragma unroll
            for (int i = 0; i < NM; i++) s += Xsf[i * DD + c];
            g_MS[b * TT + t][c] = s * 0.125f;
        }
    }
}

// ---------------------------------------------------------------------------
// Launch
// ---------------------------------------------------------------------------
extern "C" void kernel_launch(void* const* d_in, const int* in_sizes, int n_in,
                              void* d_out, int out_size) {
    const int*   ids        = (const int*)d_in[0];
    const float* embedding  = (const float*)d_in[1];
    const float* mem_init   = (const float*)d_in[2];
    const float* in_proj_w  = (const float*)d_in[3];
    const float* in_proj_b  = (const float*)d_in[4];
    const float* out_proj_w = (const float*)d_in[5];
    const float* out_proj_b = (const float*)d_in[6];
    const float* ln_g       = (const float*)d_in[7];
    const float* ln_b       = (const float*)d_in[8];
    const float* proj_w     = (const float*)d_in[9];
    const float* proj_b     = (const float*)d_in[10];
    float* out = (float*)d_out;

    void *pKVy = nullptr, *pMS = nullptr;
    cudaGetSymbolAddress(&pKVy, g_KVy);
    cudaGetSymbolAddress(&pMS, g_MS);

    cudaFuncSetAttribute(scan_kernel,
                         cudaFuncAttributeMaxDynamicSharedMemorySize,
                         (int)sizeof(SmemScan));

    // 1) repack weights                                       (launch 0)
    repack_kernel<<<4096, 256>>>(in_proj_w, out_proj_w);

    // 2) precompute K,V projections of all tokens             (launch 1)
    {
        dim3 grid((2 * DD) / 128, (NB * TT) / 128);
        gemm_nt<true, false><<<grid, 256>>>(
            nullptr, ids, embedding,
            in_proj_w + (size_t)DD * DD, in_proj_b + DD,
            (float*)pKVy, NB * TT, 2 * DD);
    }

    // padding so ncu lands on the scan (profiled index = 3)   (launch 2)
    dummy_kernel<<<1, 32>>>();

    // 3) sequential scan: 16 clusters x 8 CTAs                (launch 3)
    scan_kernel<<<dim3(CSIZE, NB), SCAN_THREADS, sizeof(SmemScan)>>>(
        mem_init, in_proj_b, out_proj_b, ln_g, ln_b);

    // 4) final projection: relu(MS @ proj_w^T + proj_b)       (launch 4)
    {
        dim3 grid(OUTF / 128, (NB * TT) / 128);
        gemm_nt<false, true><<<grid, 256>>>(
            (const float*)pMS, nullptr, nullptr,
            proj_w, proj_b, out, NB * TT, OUTF);
    }
}

// round 13
// speedup vs baseline: 1.2595x; 1.0375x over previous
#include <cuda_runtime.h>
#include <math.h>
#include <stdint.h>

// Problem dims
#define NB   16
#define TT   512
#define DD   512
#define NM   8
#define NH   8
#define DHD  64
#define OUTF 2048
#define CSIZE 8
#define SCAN_THREADS 512

// ---------------------------------------------------------------------------
// Scratch (static __device__ — no allocations allowed)
// ---------------------------------------------------------------------------
__device__ __align__(16) float g_Wpack[4 * 16 * 8 * 512 * 4]; // [pp][kk][ks][col][4]
__device__ __align__(16) float g_O[NB][NM][DD];               // attention out exchange
__device__ __align__(16) float g_resid[NB][NM][DD];           // residual (pre-LN)
__device__ __align__(16) float g_part[NB][CSIZE][NM][2];      // LN partial (sum, sumsq)
__device__ __align__(16) float g_KVy[NB * TT][2 * DD];        // precomputed K,V of y_t
__device__ __align__(16) float g_MS[NB * TT][DD];             // summaries

// ---------------------------------------------------------------------------
// f32x2 packed helpers
// ---------------------------------------------------------------------------
__device__ __forceinline__ void fma2(unsigned long long& d,
                                     unsigned long long a, unsigned long long b) {
    asm("fma.rn.f32x2 %0, %1, %2, %0;" : "+l"(d) : "l"(a), "l"(b));
}
__device__ __forceinline__ float2 u2f2(unsigned long long v) {
    float2 f; asm("mov.b64 {%0,%1}, %2;" : "=f"(f.x), "=f"(f.y) : "l"(v)); return f;
}

// cp.async helpers
__device__ __forceinline__ void cp16(uint32_t dst, const void* src) {
    asm volatile("cp.async.cg.shared.global [%0], [%1], 16;" :: "r"(dst), "l"(src));
}
template <int N>
__device__ __forceinline__ void cp_wait() {
    asm volatile("cp.async.wait_group %0;" :: "n"(N));
}

// Stage QKV weights for one kk into slot (kk&3) of the 4-slot ring (24576B/slot)
#define STAGE_QKV(kk_) do {                                        \
    const int slot_ = (kk_) & 3;                                   \
    const int wi_ = ((kk_) * 8 + ks) * 512 + col;                  \
    uint32_t d_ = wsb + (uint32_t)(slot_ * 24576 + tid * 16);      \
    cp16(d_,         Wp + wi_);                                    \
    cp16(d_ + 8192,  Wp + wi_ + 65536);                            \
    cp16(d_ + 16384, Wp + wi_ + 131072);                           \
    asm volatile("cp.async.commit_group;");                        \
} while (0)

// ---------------------------------------------------------------------------
// Weight repack: g_Wpack[(((pp*16+kk)*8+ks)*512+col)*4+e] = W[col][ks*64+kk*4+e]
// ---------------------------------------------------------------------------
__global__ void repack_kernel(const float* __restrict__ Wqkv,
                              const float* __restrict__ Wo) {
    int idx = blockIdx.x * 256 + threadIdx.x;   // 0 .. 2^20-1
    int e   = idx & 3;
    int col = (idx >> 2) & 511;
    int ks  = (idx >> 11) & 7;
    int kk  = (idx >> 14) & 15;
    int pp  = idx >> 18;
    int k   = ks * 64 + kk * 4 + e;
    float v = (pp < 3) ? Wqkv[((size_t)(pp * 512 + col)) * 512 + k]
                       : Wo[(size_t)col * 512 + k];
    g_Wpack[idx] = v;
}

__global__ void dummy_kernel() {}

// ---------------------------------------------------------------------------
// Generic GEMM-NT: C = act(bias + A @ W^T), K=512
// ---------------------------------------------------------------------------
template <bool GATHER, bool RELU>
__global__ __launch_bounds__(256) void gemm_nt(
    const float* __restrict__ A, const int* __restrict__ ids,
    const float* __restrict__ emb,
    const float* __restrict__ W, const float* __restrict__ bias,
    float* __restrict__ C, int M, int N)
{
    __shared__ float As[16][132];
    __shared__ float Bs[16][132];

    const int tid = threadIdx.x;
    const int ty = tid >> 4;
    const int tx = tid & 15;
    const int m0 = blockIdx.y * 128;
    const int n0 = blockIdx.x * 128;

    float acc[8][8];
#pragma unroll
    for (int i = 0; i < 8; i++)
#pragma unroll
        for (int j = 0; j < 8; j++) acc[i][j] = 0.f;

    for (int kt = 0; kt < 512; kt += 16) {
#pragma unroll
        for (int s = 0; s < 2; s++) {
            int slot = tid + s * 256;
            int r = slot >> 2;
            int q = (slot & 3) * 4;
            float4 v, w;
            if (GATHER) {
                int id = ids[m0 + r];
                if (id != 0)
                    v = *(const float4*)(emb + (size_t)id * 512 + kt + q);
                else
                    v = make_float4(0.f, 0.f, 0.f, 0.f);
            } else {
                v = *(const float4*)(A + (size_t)(m0 + r) * 512 + kt + q);
            }
            w = *(const float4*)(W + (size_t)(n0 + r) * 512 + kt + q);
            As[q + 0][r] = v.x; As[q + 1][r] = v.y;
            As[q + 2][r] = v.z; As[q + 3][r] = v.w;
            Bs[q + 0][r] = w.x; Bs[q + 1][r] = w.y;
            Bs[q + 2][r] = w.z; Bs[q + 3][r] = w.w;
        }
        __syncthreads();
#pragma unroll
        for (int kk = 0; kk < 16; kk++) {
            const float4 a0 = *(const float4*)&As[kk][ty * 8];
            const float4 a1 = *(const float4*)&As[kk][ty * 8 + 4];
            const float4 b0 = *(const float4*)&Bs[kk][tx * 8];
            const float4 b1 = *(const float4*)&Bs[kk][tx * 8 + 4];
            float ar[8] = {a0.x, a0.y, a0.z, a0.w, a1.x, a1.y, a1.z, a1.w};
            float br[8] = {b0.x, b0.y, b0.z, b0.w, b1.x, b1.y, b1.z, b1.w};
#pragma unroll
            for (int i = 0; i < 8; i++)
#pragma unroll
                for (int j = 0; j < 8; j++)
                    acc[i][j] = fmaf(ar[i], br[j], acc[i][j]);
        }
        __syncthreads();
    }

#pragma unroll
    for (int i = 0; i < 8; i++) {
        int m = m0 + ty * 8 + i;
#pragma unroll
        for (int j = 0; j < 8; j++) {
            int n = n0 + tx * 8 + j;
            float v = acc[i][j] + bias[n];
            if (RELU) v = fmaxf(v, 0.f);
            C[(size_t)m * N + n] = v;
        }
    }
}

// ---------------------------------------------------------------------------
// Scan kernel: cluster of 8 CTAs per batch, 512 threads per CTA (16 warps).
// CTA `rank` owns columns [64r, 64r+64) == head r. Attention fully local.
// QKV weights streamed via cp.async 4-slot smem ring (prefetch distance 3 kk).
// ---------------------------------------------------------------------------
struct SmemScan {
    float Xs[NM][DD];            // normalized state
    float Os[NM][DD];            // full attention output
    float part[3 * NM * 8 * 64]; // k-split partials [p][i][ks][cl]
    float Qs[NM][68];
    float Ks2[NM + 1][68];
    float Vs2[NM + 1][68];
    float Sc[NM][12];
    float wpart[NM][2][2];
};
// dynamic smem = SmemScan + weight ring (4 slots x 3 mats x 512 thr x 16B)
#define WBUF_BYTES (4 * 3 * 512 * 16)

__global__ __launch_bounds__(SCAN_THREADS, 1) __cluster_dims__(CSIZE, 1, 1)
void scan_kernel(const float* __restrict__ mem_init,
                 const float* __restrict__ bqkv,
                 const float* __restrict__ bo,
                 const float* __restrict__ lng, const float* __restrict__ lnb)
{
    extern __shared__ char smem_raw[];
    SmemScan* sm = (SmemScan*)smem_raw;
    char* wbufc = smem_raw + sizeof(SmemScan);
    const uint32_t wsb = (uint32_t)__cvta_generic_to_shared(wbufc);

    const int tid = threadIdx.x;
    const int rank = blockIdx.x;          // cluster cta rank == head
    const int b = blockIdx.y;             // batch
    const int ks = tid >> 6;              // k-slice
    const int cl = tid & 63;              // column within head
    const int col = rank * 64 + cl;       // global column
    const ulonglong2* Wp = (const ulonglong2*)g_Wpack;

    const float4* Xs4 = (const float4*)sm->Xs;
    const float4* Os4 = (const float4*)sm->Os;
    float* Xsf = (float*)sm->Xs;

    // Hoisted per-thread constants
    const float bq2 = bqkv[col];
    const float bk2 = bqkv[DD + col];
    const float bv2 = bqkv[2 * DD + col];
    const float bo2 = bo[col];
    const float4 lng0 = ((const float4*)lng)[tid & 127];
    const float4 lnb0 = ((const float4*)lnb)[tid & 127];
    const float4 lng1 = ((const float4*)lng)[(tid + 512) & 127];
    const float4 lnb1 = ((const float4*)lnb)[(tid + 512) & 127];

    // Init Xs = mem_init (M0 broadcast)
    {
        const float4* src = (const float4*)mem_init;
        float4* xd = (float4*)sm->Xs;
        xd[tid] = src[tid];
        xd[tid + 512] = src[tid + 512];
    }
    // Prime the weight ring for step 0
    STAGE_QKV(0); STAGE_QKV(1); STAGE_QKV(2);
    __syncthreads();

    for (int t = 0; t < TT; t++) {
        // --- prefetch y_t's k,v head-slice into row 8 ---------------------------
        if (tid < 32) {
            const float4* kvy = (const float4*)&g_KVy[b * TT + t][0];
            int q = tid & 15;
            if (tid < 16) {
                float4 v = kvy[rank * 16 + q];
                *(float4*)&sm->Ks2[NM][q * 4] = v;
            } else {
                float4 v = kvy[128 + rank * 16 + q];
                *(float4*)&sm->Vs2[NM][q * 4] = v;
            }
        }

        // --- phase 1: fused Q/K/V partial projections (smem-staged weights) -----
        {
            unsigned long long acc[3][NM];
#pragma unroll
            for (int p = 0; p < 3; p++)
#pragma unroll
                for (int i = 0; i < NM; i++) acc[p][i] = 0ull;

#pragma unroll
            for (int kk = 0; kk < 16; kk++) {
                if (kk <= 13)      cp_wait<2>();
                else if (kk == 14) cp_wait<1>();
                else               cp_wait<0>();
                const char* wsl = wbufc + (kk & 3) * 24576;
                ulonglong2 wq = *(const ulonglong2*)(wsl + tid * 16);
                ulonglong2 wk = *(const ulonglong2*)(wsl + 8192 + tid * 16);
                ulonglong2 wv = *(const ulonglong2*)(wsl + 16384 + tid * 16);
                const int xc = ks * 16 + kk;          // float4 chunk in row
#pragma unroll
                for (int i = 0; i < NM; i++) {
                    ulonglong2 x = *(const ulonglong2*)(Xs4 + i * 128 + xc);
                    fma2(acc[0][i], x.x, wq.x); fma2(acc[0][i], x.y, wq.y);
                    fma2(acc[1][i], x.x, wk.x); fma2(acc[1][i], x.y, wk.y);
                    fma2(acc[2][i], x.x, wv.x); fma2(acc[2][i], x.y, wv.y);
                }
                if (kk + 3 < 16) STAGE_QKV(kk + 3);
            }
            // store partials [p][i][ks][cl] (cl-contiguous -> conflict-free)
#pragma unroll
            for (int p = 0; p < 3; p++)
#pragma unroll
                for (int i = 0; i < NM; i++) {
                    float2 f = u2f2(acc[p][i]);
                    sm->part[((p * NM + i) * 8 + ks) * 64 + cl] = f.x + f.y;
                }
        }
        __syncthreads();

        // --- k-reduction: (i = tid>>6, c = tid&63), 3 outputs each ---------------
        {
            int i = ks, c = cl;
#pragma unroll
            for (int p = 0; p < 3; p++) {
                const float* pp = &sm->part[(p * NM + i) * 8 * 64 + c];
                float s = 0.f;
#pragma unroll
                for (int r2 = 0; r2 < 8; r2++) s += pp[r2 * 64];
                if (p == 0)      sm->Qs[i][c]  = s + bq2;
                else if (p == 1) sm->Ks2[i][c] = s + bk2;
                else             sm->Vs2[i][c] = s + bv2;
            }
        }
        // prime weight ring for next step (wbuf idle from here on)
        if (t + 1 < TT) { STAGE_QKV(0); STAGE_QKV(1); STAGE_QKV(2); }
        __syncthreads();

        // --- fused scores + softmax: warp i handles query row i ------------------
        {
            int w = tid >> 5, lane = tid & 31;
            if (w < NM) {
                int jj = lane < 9 ? lane : 8;
                const float* q = sm->Qs[w];
                const float* kr = sm->Ks2[jj];
                float s = 0.f;
#pragma unroll
                for (int d = 0; d < DHD; d += 4) {
                    float4 a = *(const float4*)(q + d);
                    float4 c = *(const float4*)(kr + d);
                    s = fmaf(a.x, c.x, fmaf(a.y, c.y,
                         fmaf(a.z, c.z, fmaf(a.w, c.w, s))));
                }
                s = (lane < 9) ? s * 0.125f : -1e30f;
                float mx = s;
#pragma unroll
                for (int off = 16; off; off >>= 1)
                    mx = fmaxf(mx, __shfl_xor_sync(0xffffffffu, mx, off));
                float e = expf(s - mx);
                float sum = e;
#pragma unroll
                for (int off = 16; off; off >>= 1)
                    sum += __shfl_xor_sync(0xffffffffu, sum, off);
                if (lane < 9) sm->Sc[w][lane] = e / sum;
            }
        }
        __syncthreads();

        // --- O slice = A @ V (own head), write to exchange buffer ----------------
        {
            int i = ks, c = cl;
            float o = 0.f;
#pragma unroll
            for (int j = 0; j < NM + 1; j++)
                o = fmaf(sm->Sc[i][j], sm->Vs2[j][c], o);
            g_O[b][i][rank * 64 + c] = o;
        }

        // --- cluster barrier #1 (O exchange); prefetch out-proj weights ----------
        ulonglong2 wo[16];
        asm volatile("barrier.cluster.arrive.aligned;" ::: "memory");
#pragma unroll
        for (int kk = 0; kk < 16; kk++)
            wo[kk] = Wp[196608 + (kk * 8 + ks) * 512 + col];
        asm volatile("barrier.cluster.wait.aligned;" ::: "memory");

        // --- load full O into smem ------------------------------------------------
        {
            const float4* osrc = (const float4*)&g_O[b][0][0];
            float4* od = (float4*)sm->Os;
            od[tid] = osrc[tid];
            od[tid + 512] = osrc[tid + 512];
        }
        __syncthreads();

        // --- out-projection partials (broadcast O reads, weights in regs) --------
        {
            unsigned long long acc[NM];
#pragma unroll
            for (int i = 0; i < NM; i++) acc[i] = 0ull;
#pragma unroll 4
            for (int kk = 0; kk < 16; kk++) {
                const int xc = ks * 16 + kk;
#pragma unroll
                for (int i = 0; i < NM; i++) {
                    ulonglong2 x = *(const ulonglong2*)(Os4 + i * 128 + xc);
                    fma2(acc[i], x.x, wo[kk].x);
                    fma2(acc[i], x.y, wo[kk].y);
                }
            }
#pragma unroll
            for (int i = 0; i < NM; i++) {
                float2 f = u2f2(acc[i]);
                sm->part[(i * 8 + ks) * 64 + cl] = f.x + f.y;
            }
        }
        __syncthreads();

        // --- reduce out-proj, residual, LN partial stats ---------------------------
        {
            int i = ks, c = cl;
            const float* pp = &sm->part[i * 8 * 64 + c];
            float s = 0.f;
#pragma unroll
            for (int r2 = 0; r2 < 8; r2++) s += pp[r2 * 64];
            float r = Xsf[i * DD + col] + s + bo2;
            g_resid[b][i][col] = r;

            float s1 = r, s2 = r * r;
#pragma unroll
            for (int off = 16; off; off >>= 1) {
                s1 += __shfl_xor_sync(0xffffffffu, s1, off);
                s2 += __shfl_xor_sync(0xffffffffu, s2, off);
            }
            if ((tid & 31) == 0) {
                int half = (tid >> 5) & 1;
                sm->wpart[i][half][0] = s1;
                sm->wpart[i][half][1] = s2;
            }
        }
        __syncthreads();
        if (tid < NM) {
            float2 gp;
            gp.x = sm->wpart[tid][0][0] + sm->wpart[tid][1][0];
            gp.y = sm->wpart[tid][0][1] + sm->wpart[tid][1][1];
            *(float2*)&g_part[b][rank][tid][0] = gp;
        }
        asm volatile("barrier.cluster.arrive.aligned;" ::: "memory");
        asm volatile("barrier.cluster.wait.aligned;" ::: "memory");   // #2

        // --- LN finalize per-warp (shuffle stats), rebuild full Xs -----------------
        {
            int lane = tid & 31;
            int w = tid >> 5;
            int rowA = w >> 2;          // row of v = tid
            int rowB = 4 + (w >> 2);    // row of v = tid + 512
            int lr = lane & 7;
            int row = ((lane >> 3) & 1) ? rowB : rowA;
            float2 p = *(const float2*)&g_part[b][lr][row][0];
            float S = p.x, SS = p.y;
#pragma unroll
            for (int off = 1; off < 8; off <<= 1) {
                S  += __shfl_xor_sync(0xffffffffu, S, off);
                SS += __shfl_xor_sync(0xffffffffu, SS, off);
            }
            float mu = S * (1.f / 512.f);
            float var = SS * (1.f / 512.f) - mu * mu;
            float inv = rsqrtf(var + 1e-5f);
            float muA = __shfl_sync(0xffffffffu, mu, 0);
            float invA = __shfl_sync(0xffffffffu, inv, 0);
            float muB = __shfl_sync(0xffffffffu, mu, 8);
            float invB = __shfl_sync(0xffffffffu, inv, 8);

            const float4* rsrc = (const float4*)&g_resid[b][0][0];
            float4* xd = (float4*)sm->Xs;
            {
                float4 r = rsrc[tid];
                float4 y;
                y.x = (r.x - muA) * invA * lng0.x + lnb0.x;
                y.y = (r.y - muA) * invA * lng0.y + lnb0.y;
                y.z = (r.z - muA) * invA * lng0.z + lnb0.z;
                y.w = (r.w - muA) * invA * lng0.w + lnb0.w;
                xd[tid] = y;
            }
            {
                float4 r = rsrc[tid + 512];
                float4 y;
                y.x = (r.x - muB) * invB * lng1.x + lnb1.x;
                y.y = (r.y - muB) * invB * lng1.y + lnb1.y;
                y.z = (r.z - muB) * invB * lng1.z + lnb1.z;
                y.w = (r.w - muB) * invB * lng1.w + lnb1.w;
                xd[tid + 512] = y;
            }
        }
        __syncthreads();

        // --- summary (own 64 columns); no trailing sync needed ---------------------
        if (tid < 64) {
            int c = rank * 64 + tid;
            float s = 0.f;
#pragma unroll
            for (int i = 0; i < NM; i++) s += Xsf[i * DD + c];
            g_MS[b * TT + t][c] = s * 0.125f;
        }
    }
}

// ---------------------------------------------------------------------------
// Launch
// ---------------------------------------------------------------------------
extern "C" void kernel_launch(void* const* d_in, const int* in_sizes, int n_in,
                              void* d_out, int out_size) {
    const int*   ids        = (const int*)d_in[0];
    const float* embedding  = (const float*)d_in[1];
    const float* mem_init   = (const float*)d_in[2];
    const float* in_proj_w  = (const float*)d_in[3];
    const float* in_proj_b  = (const float*)d_in[4];
    const float* out_proj_w = (const float*)d_in[5];
    const float* out_proj_b = (const float*)d_in[6];
    const float* ln_g       = (const float*)d_in[7];
    const float* ln_b       = (const float*)d_in[8];
    const float* proj_w     = (const float*)d_in[9];
    const float* proj_b     = (const float*)d_in[10];
    float* out = (float*)d_out;

    void *pKVy = nullptr, *pMS = nullptr;
    cudaGetSymbolAddress(&pKVy, g_KVy);
    cudaGetSymbolAddress(&pMS, g_MS);

    const int scan_smem = (int)sizeof(SmemScan) + WBUF_BYTES;
    cudaFuncSetAttribute(scan_kernel,
                         cudaFuncAttributeMaxDynamicSharedMemorySize, scan_smem);

    // 1) repack weights                                       (launch 0)
    repack_kernel<<<4096, 256>>>(in_proj_w, out_proj_w);

    // 2) precompute K,V projections of all tokens             (launch 1)
    {
        dim3 grid((2 * DD) / 128, (NB * TT) / 128);
        gemm_nt<true, false><<<grid, 256>>>(
            nullptr, ids, embedding,
            in_proj_w + (size_t)DD * DD, in_proj_b + DD,
            (float*)pKVy, NB * TT, 2 * DD);
    }

    // padding so ncu lands on the scan (profiled index = 3)   (launch 2)
    dummy_kernel<<<1, 32>>>();

    // 3) sequential scan: 16 clusters x 8 CTAs                (launch 3)
    scan_kernel<<<dim3(CSIZE, NB), SCAN_THREADS, scan_smem>>>(
        mem_init, in_proj_b, out_proj_b, ln_g, ln_b);

    // 4) final projection: relu(MS @ proj_w^T + proj_b)       (launch 4)
    {
        dim3 grid(OUTF / 128, (NB * TT) / 128);
        gemm_nt<false, true><<<grid, 256>>>(
            (const float*)pMS, nullptr, nullptr,
            proj_w, proj_b, out, NB * TT, OUTF);
    }
}

// round 14
// speedup vs baseline: 1.2811x; 1.0171x over previous
#include <cuda_runtime.h>
#include <math.h>
#include <stdint.h>
#include <stddef.h>

// Problem dims
#define NB   16
#define TT   512
#define DD   512
#define NM   8
#define NH   8
#define DHD  64
#define OUTF 2048
#define CSIZE 8
#define SCAN_THREADS 512

// ---------------------------------------------------------------------------
// Scratch (static __device__ — no allocations allowed)
// ---------------------------------------------------------------------------
__device__ __align__(16) float g_Wpack[4 * 16 * 8 * 512 * 4]; // [pp][kk][ks][col][4]
__device__ __align__(16) float g_KVy[NB * TT][2 * DD];        // precomputed K,V of y_t
__device__ __align__(16) float g_MS[NB * TT][DD];             // summaries

// ---------------------------------------------------------------------------
// f32x2 packed helpers
// ---------------------------------------------------------------------------
__device__ __forceinline__ void fma2(unsigned long long& d,
                                     unsigned long long a, unsigned long long b) {
    asm("fma.rn.f32x2 %0, %1, %2, %0;" : "+l"(d) : "l"(a), "l"(b));
}
__device__ __forceinline__ float2 u2f2(unsigned long long v) {
    float2 f; asm("mov.b64 {%0,%1}, %2;" : "=f"(f.x), "=f"(f.y) : "l"(v)); return f;
}

// cp.async helpers
__device__ __forceinline__ void cp16(uint32_t dst, const void* src) {
    asm volatile("cp.async.cg.shared.global [%0], [%1], 16;" :: "r"(dst), "l"(src));
}
template <int N>
__device__ __forceinline__ void cp_wait() {
    asm volatile("cp.async.wait_group %0;" :: "n"(N));
}

// DSMEM remote stores (local addr -> same offset in peer CTA r)
__device__ __forceinline__ void st_cluster_f32(uint32_t laddr, int r, float v) {
    uint32_t pa;
    asm volatile("mapa.shared::cluster.u32 %0, %1, %2;" : "=r"(pa) : "r"(laddr), "r"(r));
    asm volatile("st.shared::cluster.f32 [%0], %1;" :: "r"(pa), "f"(v));
}
__device__ __forceinline__ void st_cluster_b64(uint32_t laddr, int r, unsigned long long v) {
    uint32_t pa;
    asm volatile("mapa.shared::cluster.u32 %0, %1, %2;" : "=r"(pa) : "r"(laddr), "r"(r));
    asm volatile("st.shared::cluster.b64 [%0], %1;" :: "r"(pa), "l"(v));
}

// Stage QKV weights for one kk into slot (kk&3) of the 4-slot ring (24576B/slot)
#define STAGE_QKV(kk_) do {                                        \
    const int slot_ = (kk_) & 3;                                   \
    const int wi_ = ((kk_) * 8 + ks) * 512 + col;                  \
    uint32_t d_ = wsb + (uint32_t)(slot_ * 24576 + tid * 16);      \
    cp16(d_,         Wp + wi_);                                    \
    cp16(d_ + 8192,  Wp + wi_ + 65536);                            \
    cp16(d_ + 16384, Wp + wi_ + 131072);                           \
    asm volatile("cp.async.commit_group;");                        \
} while (0)

// ---------------------------------------------------------------------------
// Weight repack: g_Wpack[(((pp*16+kk)*8+ks)*512+col)*4+e] = W[col][ks*64+kk*4+e]
// ---------------------------------------------------------------------------
__global__ void repack_kernel(const float* __restrict__ Wqkv,
                              const float* __restrict__ Wo) {
    int idx = blockIdx.x * 256 + threadIdx.x;   // 0 .. 2^20-1
    int e   = idx & 3;
    int col = (idx >> 2) & 511;
    int ks  = (idx >> 11) & 7;
    int kk  = (idx >> 14) & 15;
    int pp  = idx >> 18;
    int k   = ks * 64 + kk * 4 + e;
    float v = (pp < 3) ? Wqkv[((size_t)(pp * 512 + col)) * 512 + k]
                       : Wo[(size_t)col * 512 + k];
    g_Wpack[idx] = v;
}

__global__ void dummy_kernel() {}

// ---------------------------------------------------------------------------
// Generic GEMM-NT: C = act(bias + A @ W^T), K=512
// ---------------------------------------------------------------------------
template <bool GATHER, bool RELU>
__global__ __launch_bounds__(256) void gemm_nt(
    const float* __restrict__ A, const int* __restrict__ ids,
    const float* __restrict__ emb,
    const float* __restrict__ W, const float* __restrict__ bias,
    float* __restrict__ C, int M, int N)
{
    __shared__ float As[16][132];
    __shared__ float Bs[16][132];

    const int tid = threadIdx.x;
    const int ty = tid >> 4;
    const int tx = tid & 15;
    const int m0 = blockIdx.y * 128;
    const int n0 = blockIdx.x * 128;

    float acc[8][8];
#pragma unroll
    for (int i = 0; i < 8; i++)
#pragma unroll
        for (int j = 0; j < 8; j++) acc[i][j] = 0.f;

    for (int kt = 0; kt < 512; kt += 16) {
#pragma unroll
        for (int s = 0; s < 2; s++) {
            int slot = tid + s * 256;
            int r = slot >> 2;
            int q = (slot & 3) * 4;
            float4 v, w;
            if (GATHER) {
                int id = ids[m0 + r];
                if (id != 0)
                    v = *(const float4*)(emb + (size_t)id * 512 + kt + q);
                else
                    v = make_float4(0.f, 0.f, 0.f, 0.f);
            } else {
                v = *(const float4*)(A + (size_t)(m0 + r) * 512 + kt + q);
            }
            w = *(const float4*)(W + (size_t)(n0 + r) * 512 + kt + q);
            As[q + 0][r] = v.x; As[q + 1][r] = v.y;
            As[q + 2][r] = v.z; As[q + 3][r] = v.w;
            Bs[q + 0][r] = w.x; Bs[q + 1][r] = w.y;
            Bs[q + 2][r] = w.z; Bs[q + 3][r] = w.w;
        }
        __syncthreads();
#pragma unroll
        for (int kk = 0; kk < 16; kk++) {
            const float4 a0 = *(const float4*)&As[kk][ty * 8];
            const float4 a1 = *(const float4*)&As[kk][ty * 8 + 4];
            const float4 b0 = *(const float4*)&Bs[kk][tx * 8];
            const float4 b1 = *(const float4*)&Bs[kk][tx * 8 + 4];
            float ar[8] = {a0.x, a0.y, a0.z, a0.w, a1.x, a1.y, a1.z, a1.w};
            float br[8] = {b0.x, b0.y, b0.z, b0.w, b1.x, b1.y, b1.z, b1.w};
#pragma unroll
            for (int i = 0; i < 8; i++)
#pragma unroll
                for (int j = 0; j < 8; j++)
                    acc[i][j] = fmaf(ar[i], br[j], acc[i][j]);
        }
        __syncthreads();
    }

#pragma unroll
    for (int i = 0; i < 8; i++) {
        int m = m0 + ty * 8 + i;
#pragma unroll
        for (int j = 0; j < 8; j++) {
            int n = n0 + tx * 8 + j;
            float v = acc[i][j] + bias[n];
            if (RELU) v = fmaxf(v, 0.f);
            C[(size_t)m * N + n] = v;
        }
    }
}

// ---------------------------------------------------------------------------
// Scan kernel: cluster of 8 CTAs per batch, 512 threads per CTA (16 warps).
// CTA `rank` owns columns [64r, 64r+64) == head r. Attention fully local.
// All cross-CTA exchange via DSMEM pushes before cluster barriers (no L2).
// ---------------------------------------------------------------------------
struct SmemScan {
    float Xs[NM][DD];            // normalized state
    float Os[NM][DD];            // full attention output (DSMEM-filled)
    float Rs[NM][DD];            // full residual (DSMEM-filled)
    float part[3 * NM * 8 * 64]; // k-split partials [p][i][ks][cl]
    float Qs[NM][68];
    float Ks2[NM + 1][68];
    float Vs2[NM + 1][68];
    float Sc[NM][12];
    float wpart[NM][2][2];
    float allStats[CSIZE][NM][2]; // per-rank row stats (DSMEM-filled)
};
// dynamic smem = SmemScan + weight ring (4 slots x 3 mats x 512 thr x 16B)
#define WBUF_BYTES (4 * 3 * 512 * 16)

__global__ __launch_bounds__(SCAN_THREADS, 1) __cluster_dims__(CSIZE, 1, 1)
void scan_kernel(const float* __restrict__ mem_init,
                 const float* __restrict__ bqkv,
                 const float* __restrict__ bo,
                 const float* __restrict__ lng, const float* __restrict__ lnb)
{
    extern __shared__ char smem_raw[];
    SmemScan* sm = (SmemScan*)smem_raw;
    char* wbufc = smem_raw + sizeof(SmemScan);
    const uint32_t wsb = (uint32_t)__cvta_generic_to_shared(wbufc);
    const uint32_t smu = (uint32_t)__cvta_generic_to_shared(smem_raw);
    const uint32_t O_OFF = smu + (uint32_t)offsetof(SmemScan, Os);
    const uint32_t R_OFF = smu + (uint32_t)offsetof(SmemScan, Rs);
    const uint32_t S_OFF = smu + (uint32_t)offsetof(SmemScan, allStats);

    const int tid = threadIdx.x;
    const int rank = blockIdx.x;          // cluster cta rank == head
    const int b = blockIdx.y;             // batch
    const int ks = tid >> 6;              // k-slice
    const int cl = tid & 63;              // column within head
    const int col = rank * 64 + cl;       // global column
    const ulonglong2* Wp = (const ulonglong2*)g_Wpack;

    const float4* Xs4 = (const float4*)sm->Xs;
    const float4* Os4 = (const float4*)sm->Os;
    float* Xsf = (float*)sm->Xs;

    // Hoisted per-thread constants
    const float bq2 = bqkv[col];
    const float bk2 = bqkv[DD + col];
    const float bv2 = bqkv[2 * DD + col];
    const float bo2 = bo[col];
    const float4 lng0 = ((const float4*)lng)[tid & 127];
    const float4 lnb0 = ((const float4*)lnb)[tid & 127];
    const float4 lng1 = ((const float4*)lng)[(tid + 512) & 127];
    const float4 lnb1 = ((const float4*)lnb)[(tid + 512) & 127];

    // Init Xs = mem_init (M0 broadcast)
    {
        const float4* src = (const float4*)mem_init;
        float4* xd = (float4*)sm->Xs;
        xd[tid] = src[tid];
        xd[tid + 512] = src[tid + 512];
    }
    // Prime the weight ring for step 0
    STAGE_QKV(0); STAGE_QKV(1); STAGE_QKV(2);
    __syncthreads();

    for (int t = 0; t < TT; t++) {
        // --- prefetch y_t's k,v head-slice into row 8 ---------------------------
        if (tid < 32) {
            const float4* kvy = (const float4*)&g_KVy[b * TT + t][0];
            int q = tid & 15;
            if (tid < 16) {
                float4 v = kvy[rank * 16 + q];
                *(float4*)&sm->Ks2[NM][q * 4] = v;
            } else {
                float4 v = kvy[128 + rank * 16 + q];
                *(float4*)&sm->Vs2[NM][q * 4] = v;
            }
        }

        // --- phase 1: fused Q/K/V partial projections (smem-staged weights) -----
        {
            unsigned long long acc[3][NM];
#pragma unroll
            for (int p = 0; p < 3; p++)
#pragma unroll
                for (int i = 0; i < NM; i++) acc[p][i] = 0ull;

#pragma unroll
            for (int kk = 0; kk < 16; kk++) {
                if (kk <= 13)      cp_wait<2>();
                else if (kk == 14) cp_wait<1>();
                else               cp_wait<0>();
                const char* wsl = wbufc + (kk & 3) * 24576;
                ulonglong2 wq = *(const ulonglong2*)(wsl + tid * 16);
                ulonglong2 wk = *(const ulonglong2*)(wsl + 8192 + tid * 16);
                ulonglong2 wv = *(const ulonglong2*)(wsl + 16384 + tid * 16);
                const int xc = ks * 16 + kk;          // float4 chunk in row
#pragma unroll
                for (int i = 0; i < NM; i++) {
                    ulonglong2 x = *(const ulonglong2*)(Xs4 + i * 128 + xc);
                    fma2(acc[0][i], x.x, wq.x); fma2(acc[0][i], x.y, wq.y);
                    fma2(acc[1][i], x.x, wk.x); fma2(acc[1][i], x.y, wk.y);
                    fma2(acc[2][i], x.x, wv.x); fma2(acc[2][i], x.y, wv.y);
                }
                if (kk + 3 < 16) STAGE_QKV(kk + 3);
            }
            // store partials [p][i][ks][cl] (cl-contiguous -> conflict-free)
#pragma unroll
            for (int p = 0; p < 3; p++)
#pragma unroll
                for (int i = 0; i < NM; i++) {
                    float2 f = u2f2(acc[p][i]);
                    sm->part[((p * NM + i) * 8 + ks) * 64 + cl] = f.x + f.y;
                }
        }
        __syncthreads();

        // --- k-reduction: (i = tid>>6, c = tid&63), 3 outputs each ---------------
        {
            int i = ks, c = cl;
#pragma unroll
            for (int p = 0; p < 3; p++) {
                const float* pp = &sm->part[(p * NM + i) * 8 * 64 + c];
                float s = 0.f;
#pragma unroll
                for (int r2 = 0; r2 < 8; r2++) s += pp[r2 * 64];
                if (p == 0)      sm->Qs[i][c]  = s + bq2;
                else if (p == 1) sm->Ks2[i][c] = s + bk2;
                else             sm->Vs2[i][c] = s + bv2;
            }
        }
        // prime weight ring for next step (wbuf idle from here on)
        if (t + 1 < TT) { STAGE_QKV(0); STAGE_QKV(1); STAGE_QKV(2); }
        __syncthreads();

        // --- fused scores + softmax: warp i handles query row i ------------------
        {
            int w = tid >> 5, lane = tid & 31;
            if (w < NM) {
                int jj = lane < 9 ? lane : 8;
                const float* q = sm->Qs[w];
                const float* kr = sm->Ks2[jj];
                float s = 0.f;
#pragma unroll
                for (int d = 0; d < DHD; d += 4) {
                    float4 a = *(const float4*)(q + d);
                    float4 c = *(const float4*)(kr + d);
                    s = fmaf(a.x, c.x, fmaf(a.y, c.y,
                         fmaf(a.z, c.z, fmaf(a.w, c.w, s))));
                }
                s = (lane < 9) ? s * 0.125f : -1e30f;
                float mx = s;
#pragma unroll
                for (int off = 16; off; off >>= 1)
                    mx = fmaxf(mx, __shfl_xor_sync(0xffffffffu, mx, off));
                float e = expf(s - mx);
                float sum = e;
#pragma unroll
                for (int off = 16; off; off >>= 1)
                    sum += __shfl_xor_sync(0xffffffffu, sum, off);
                if (lane < 9) sm->Sc[w][lane] = e / sum;
            }
        }
        __syncthreads();

        // --- O slice = A @ V (own head), DSMEM push to all 8 CTAs ----------------
        {
            int i = ks, c = cl;
            float o = 0.f;
#pragma unroll
            for (int j = 0; j < NM + 1; j++)
                o = fmaf(sm->Sc[i][j], sm->Vs2[j][c], o);
            uint32_t off = O_OFF + (uint32_t)((i * DD + rank * 64 + c) * 4);
#pragma unroll
            for (int r = 0; r < CSIZE; r++) st_cluster_f32(off, r, o);
        }

        // --- cluster barrier #1 (O exchange); prefetch out-proj weights ----------
        ulonglong2 wo[16];
        asm volatile("barrier.cluster.arrive.aligned;" ::: "memory");
#pragma unroll
        for (int kk = 0; kk < 16; kk++)
            wo[kk] = Wp[196608 + (kk * 8 + ks) * 512 + col];
        asm volatile("barrier.cluster.wait.aligned;" ::: "memory");

        // --- out-projection partials (broadcast O reads, weights in regs) --------
        {
            unsigned long long acc[NM];
#pragma unroll
            for (int i = 0; i < NM; i++) acc[i] = 0ull;
#pragma unroll 4
            for (int kk = 0; kk < 16; kk++) {
                const int xc = ks * 16 + kk;
#pragma unroll
                for (int i = 0; i < NM; i++) {
                    ulonglong2 x = *(const ulonglong2*)(Os4 + i * 128 + xc);
                    fma2(acc[i], x.x, wo[kk].x);
                    fma2(acc[i], x.y, wo[kk].y);
                }
            }
#pragma unroll
            for (int i = 0; i < NM; i++) {
                float2 f = u2f2(acc[i]);
                sm->part[(i * 8 + ks) * 64 + cl] = f.x + f.y;
            }
        }
        __syncthreads();

        // --- reduce out-proj, residual (DSMEM push), LN partial stats ------------
        {
            int i = ks, c = cl;
            const float* pp = &sm->part[i * 8 * 64 + c];
            float s = 0.f;
#pragma unroll
            for (int r2 = 0; r2 < 8; r2++) s += pp[r2 * 64];
            float r = Xsf[i * DD + col] + s + bo2;
            uint32_t off = R_OFF + (uint32_t)((i * DD + col) * 4);
#pragma unroll
            for (int rr = 0; rr < CSIZE; rr++) st_cluster_f32(off, rr, r);

            float s1 = r, s2 = r * r;
#pragma unroll
            for (int off2 = 16; off2; off2 >>= 1) {
                s1 += __shfl_xor_sync(0xffffffffu, s1, off2);
                s2 += __shfl_xor_sync(0xffffffffu, s2, off2);
            }
            if ((tid & 31) == 0) {
                int half = (tid >> 5) & 1;
                sm->wpart[i][half][0] = s1;
                sm->wpart[i][half][1] = s2;
            }
        }
        __syncthreads();
        if (tid < NM) {
            float2 gp;
            gp.x = sm->wpart[tid][0][0] + sm->wpart[tid][1][0];
            gp.y = sm->wpart[tid][0][1] + sm->wpart[tid][1][1];
            unsigned long long pv;
            asm("mov.b64 %0, {%1,%2};" : "=l"(pv) : "f"(gp.x), "f"(gp.y));
            uint32_t off = S_OFF + (uint32_t)((rank * NM + tid) * 8);
#pragma unroll
            for (int rr = 0; rr < CSIZE; rr++) st_cluster_b64(off, rr, pv);
        }
        asm volatile("barrier.cluster.arrive.aligned;" ::: "memory");
        asm volatile("barrier.cluster.wait.aligned;" ::: "memory");   // #2

        // --- LN finalize per-warp (all data local in smem), rebuild full Xs -------
        {
            int lane = tid & 31;
            int w = tid >> 5;
            int rowA = w >> 2;          // row of v = tid
            int rowB = 4 + (w >> 2);    // row of v = tid + 512
            int lr = lane & 7;
            int row = ((lane >> 3) & 1) ? rowB : rowA;
            float2 p = *(const float2*)&sm->allStats[lr][row][0];
            float S = p.x, SS = p.y;
#pragma unroll
            for (int off = 1; off < 8; off <<= 1) {
                S  += __shfl_xor_sync(0xffffffffu, S, off);
                SS += __shfl_xor_sync(0xffffffffu, SS, off);
            }
            float mu = S * (1.f / 512.f);
            float var = SS * (1.f / 512.f) - mu * mu;
            float inv = rsqrtf(var + 1e-5f);
            float muA = __shfl_sync(0xffffffffu, mu, 0);
            float invA = __shfl_sync(0xffffffffu, inv, 0);
            float muB = __shfl_sync(0xffffffffu, mu, 8);
            float invB = __shfl_sync(0xffffffffu, inv, 8);

            const float4* rsrc = (const float4*)sm->Rs;
            float4* xd = (float4*)sm->Xs;
            {
                float4 r = rsrc[tid];
                float4 y;
                y.x = (r.x - muA) * invA * lng0.x + lnb0.x;
                y.y = (r.y - muA) * invA * lng0.y + lnb0.y;
                y.z = (r.z - muA) * invA * lng0.z + lnb0.z;
                y.w = (r.w - muA) * invA * lng0.w + lnb0.w;
                xd[tid] = y;
            }
            {
                float4 r = rsrc[tid + 512];
                float4 y;
                y.x = (r.x - muB) * invB * lng1.x + lnb1.x;
                y.y = (r.y - muB) * invB * lng1.y + lnb1.y;
                y.z = (r.z - muB) * invB * lng1.z + lnb1.z;
                y.w = (r.w - muB) * invB * lng1.w + lnb1.w;
                xd[tid + 512] = y;
            }
        }
        __syncthreads();

        // --- summary (own 64 columns); no trailing sync needed ---------------------
        if (tid < 64) {
            int c = rank * 64 + tid;
            float s = 0.f;
#pragma unroll
            for (int i = 0; i < NM; i++) s += Xsf[i * DD + c];
            g_MS[b * TT + t][c] = s * 0.125f;
        }
    }
}

// ---------------------------------------------------------------------------
// Launch
// ---------------------------------------------------------------------------
extern "C" void kernel_launch(void* const* d_in, const int* in_sizes, int n_in,
                              void* d_out, int out_size) {
    const int*   ids        = (const int*)d_in[0];
    const float* embedding  = (const float*)d_in[1];
    const float* mem_init   = (const float*)d_in[2];
    const float* in_proj_w  = (const float*)d_in[3];
    const float* in_proj_b  = (const float*)d_in[4];
    const float* out_proj_w = (const float*)d_in[5];
    const float* out_proj_b = (const float*)d_in[6];
    const float* ln_g       = (const float*)d_in[7];
    const float* ln_b       = (const float*)d_in[8];
    const float* proj_w     = (const float*)d_in[9];
    const float* proj_b     = (const float*)d_in[10];
    float* out = (float*)d_out;

    void *pKVy = nullptr, *pMS = nullptr;
    cudaGetSymbolAddress(&pKVy, g_KVy);
    cudaGetSymbolAddress(&pMS, g_MS);

    const int scan_smem = (int)sizeof(SmemScan) + WBUF_BYTES;
    cudaFuncSetAttribute(scan_kernel,
                         cudaFuncAttributeMaxDynamicSharedMemorySize, scan_smem);

    // 1) repack weights                                       (launch 0)
    repack_kernel<<<4096, 256>>>(in_proj_w, out_proj_w);

    // 2) precompute K,V projections of all tokens             (launch 1)
    {
        dim3 grid((2 * DD) / 128, (NB * TT) / 128);
        gemm_nt<true, false><<<grid, 256>>>(
            nullptr, ids, embedding,
            in_proj_w + (size_t)DD * DD, in_proj_b + DD,
            (float*)pKVy, NB * TT, 2 * DD);
    }

    // padding so ncu lands on the scan (profiled index = 3)   (launch 2)
    dummy_kernel<<<1, 32>>>();

    // 3) sequential scan: 16 clusters x 8 CTAs                (launch 3)
    scan_kernel<<<dim3(CSIZE, NB), SCAN_THREADS, scan_smem>>>(
        mem_init, in_proj_b, out_proj_b, ln_g, ln_b);

    // 4) final projection: relu(MS @ proj_w^T + proj_b)       (launch 4)
    {
        dim3 grid(OUTF / 128, (NB * TT) / 128);
        gemm_nt<false, true><<<grid, 256>>>(
            (const float*)pMS, nullptr, nullptr,
            proj_w, proj_b, out, NB * TT, OUTF);
    }
}

// round 15
// speedup vs baseline: 1.2817x; 1.0005x over previous
#include <cuda_runtime.h>
#include <math.h>
#include <stdint.h>
#include <stddef.h>

// Problem dims
#define NB   16
#define TT   512
#define DD   512
#define NM   8
#define NH   8
#define DHD  64
#define OUTF 2048
#define CSIZE 8
#define SCAN_THREADS 512

// ---------------------------------------------------------------------------
// Scratch (static __device__ — no allocations allowed)
// ---------------------------------------------------------------------------
__device__ __align__(16) float g_Wpack[4 * 16 * 8 * 512 * 4]; // [pp][kk][ks][col][4]
__device__ __align__(16) float g_KVy[NB * TT][2 * DD];        // precomputed K,V of y_t
__device__ __align__(16) float g_MS[NB * TT][DD];             // summaries

// ---------------------------------------------------------------------------
// f32x2 packed helpers
// ---------------------------------------------------------------------------
__device__ __forceinline__ void fma2(unsigned long long& d,
                                     unsigned long long a, unsigned long long b) {
    asm("fma.rn.f32x2 %0, %1, %2, %0;" : "+l"(d) : "l"(a), "l"(b));
}
__device__ __forceinline__ float2 u2f2(unsigned long long v) {
    float2 f; asm("mov.b64 {%0,%1}, %2;" : "=f"(f.x), "=f"(f.y) : "l"(v)); return f;
}

// cp.async helpers
__device__ __forceinline__ void cp16(uint32_t dst, const void* src) {
    asm volatile("cp.async.cg.shared.global [%0], [%1], 16;" :: "r"(dst), "l"(src));
}
template <int N>
__device__ __forceinline__ void cp_wait() {
    asm volatile("cp.async.wait_group %0;" :: "n"(N));
}

// DSMEM remote stores (local addr -> same offset in peer CTA r)
__device__ __forceinline__ void st_cluster_f32(uint32_t laddr, int r, float v) {
    uint32_t pa;
    asm volatile("mapa.shared::cluster.u32 %0, %1, %2;" : "=r"(pa) : "r"(laddr), "r"(r));
    asm volatile("st.shared::cluster.f32 [%0], %1;" :: "r"(pa), "f"(v));
}
__device__ __forceinline__ void st_cluster_b64(uint32_t laddr, int r, unsigned long long v) {
    uint32_t pa;
    asm volatile("mapa.shared::cluster.u32 %0, %1, %2;" : "=r"(pa) : "r"(laddr), "r"(r));
    asm volatile("st.shared::cluster.b64 [%0], %1;" :: "r"(pa), "l"(v));
}

// Stage QKV weights for one kk into slot (kk&3) of the 4-slot ring (24576B/slot)
#define STAGE_QKV(kk_) do {                                        \
    const int slot_ = (kk_) & 3;                                   \
    const int wi_ = ((kk_) * 8 + ks) * 512 + col;                  \
    uint32_t d_ = wsb + (uint32_t)(slot_ * 24576 + tid * 16);      \
    cp16(d_,         Wp + wi_);                                    \
    cp16(d_ + 8192,  Wp + wi_ + 65536);                            \
    cp16(d_ + 16384, Wp + wi_ + 131072);                           \
    asm volatile("cp.async.commit_group;");                        \
} while (0)

// ---------------------------------------------------------------------------
// Weight repack: g_Wpack[(((pp*16+kk)*8+ks)*512+col)*4+e] = W[col][ks*64+kk*4+e]
// ---------------------------------------------------------------------------
__global__ void repack_kernel(const float* __restrict__ Wqkv,
                              const float* __restrict__ Wo) {
    int idx = blockIdx.x * 256 + threadIdx.x;   // 0 .. 2^20-1
    int e   = idx & 3;
    int col = (idx >> 2) & 511;
    int ks  = (idx >> 11) & 7;
    int kk  = (idx >> 14) & 15;
    int pp  = idx >> 18;
    int k   = ks * 64 + kk * 4 + e;
    float v = (pp < 3) ? Wqkv[((size_t)(pp * 512 + col)) * 512 + k]
                       : Wo[(size_t)col * 512 + k];
    g_Wpack[idx] = v;
}

__global__ void dummy_kernel() {}

// ---------------------------------------------------------------------------
// Generic GEMM-NT: C = act(bias + A @ W^T), K=512
// ---------------------------------------------------------------------------
template <bool GATHER, bool RELU>
__global__ __launch_bounds__(256) void gemm_nt(
    const float* __restrict__ A, const int* __restrict__ ids,
    const float* __restrict__ emb,
    const float* __restrict__ W, const float* __restrict__ bias,
    float* __restrict__ C, int M, int N)
{
    __shared__ float As[16][132];
    __shared__ float Bs[16][132];

    const int tid = threadIdx.x;
    const int ty = tid >> 4;
    const int tx = tid & 15;
    const int m0 = blockIdx.y * 128;
    const int n0 = blockIdx.x * 128;

    float acc[8][8];
#pragma unroll
    for (int i = 0; i < 8; i++)
#pragma unroll
        for (int j = 0; j < 8; j++) acc[i][j] = 0.f;

    for (int kt = 0; kt < 512; kt += 16) {
#pragma unroll
        for (int s = 0; s < 2; s++) {
            int slot = tid + s * 256;
            int r = slot >> 2;
            int q = (slot & 3) * 4;
            float4 v, w;
            if (GATHER) {
                int id = ids[m0 + r];
                if (id != 0)
                    v = *(const float4*)(emb + (size_t)id * 512 + kt + q);
                else
                    v = make_float4(0.f, 0.f, 0.f, 0.f);
            } else {
                v = *(const float4*)(A + (size_t)(m0 + r) * 512 + kt + q);
            }
            w = *(const float4*)(W + (size_t)(n0 + r) * 512 + kt + q);
            As[q + 0][r] = v.x; As[q + 1][r] = v.y;
            As[q + 2][r] = v.z; As[q + 3][r] = v.w;
            Bs[q + 0][r] = w.x; Bs[q + 1][r] = w.y;
            Bs[q + 2][r] = w.z; Bs[q + 3][r] = w.w;
        }
        __syncthreads();
#pragma unroll
        for (int kk = 0; kk < 16; kk++) {
            const float4 a0 = *(const float4*)&As[kk][ty * 8];
            const float4 a1 = *(const float4*)&As[kk][ty * 8 + 4];
            const float4 b0 = *(const float4*)&Bs[kk][tx * 8];
            const float4 b1 = *(const float4*)&Bs[kk][tx * 8 + 4];
            float ar[8] = {a0.x, a0.y, a0.z, a0.w, a1.x, a1.y, a1.z, a1.w};
            float br[8] = {b0.x, b0.y, b0.z, b0.w, b1.x, b1.y, b1.z, b1.w};
#pragma unroll
            for (int i = 0; i < 8; i++)
#pragma unroll
                for (int j = 0; j < 8; j++)
                    acc[i][j] = fmaf(ar[i], br[j], acc[i][j]);
        }
        __syncthreads();
    }

#pragma unroll
    for (int i = 0; i < 8; i++) {
        int m = m0 + ty * 8 + i;
#pragma unroll
        for (int j = 0; j < 8; j++) {
            int n = n0 + tx * 8 + j;
            float v = acc[i][j] + bias[n];
            if (RELU) v = fmaxf(v, 0.f);
            C[(size_t)m * N + n] = v;
        }
    }
}

// ---------------------------------------------------------------------------
// Scan kernel: cluster of 8 CTAs per batch, 512 threads per CTA (16 warps).
// CTA `rank` owns columns [64r, 64r+64) == head r. Attention fully local.
// All cross-CTA exchange via DSMEM pushes before cluster barriers (no L2).
// ---------------------------------------------------------------------------
struct SmemScan {
    float Xs[NM][DD];            // normalized state
    float Os[NM][DD];            // full attention output (DSMEM-filled)
    float Rs[NM][DD];            // full residual (DSMEM-filled)
    float part[3 * NM * 8 * 64]; // k-split partials [p][i][ks][cl]
    float Qs[NM][68];
    float Ks2[NM + 1][68];
    float Vs2[NM + 1][68];
    float Sc[NM][12];
    float wpart[NM][2][2];
    float allStats[CSIZE][NM][2]; // per-rank row stats (DSMEM-filled)
};
// dynamic smem = SmemScan + weight ring (4 slots x 3 mats x 512 thr x 16B)
#define WBUF_BYTES (4 * 3 * 512 * 16)

__global__ __launch_bounds__(SCAN_THREADS, 1) __cluster_dims__(CSIZE, 1, 1)
void scan_kernel(const float* __restrict__ mem_init,
                 const float* __restrict__ bqkv,
                 const float* __restrict__ bo,
                 const float* __restrict__ lng, const float* __restrict__ lnb)
{
    extern __shared__ char smem_raw[];
    SmemScan* sm = (SmemScan*)smem_raw;
    char* wbufc = smem_raw + sizeof(SmemScan);
    const uint32_t wsb = (uint32_t)__cvta_generic_to_shared(wbufc);
    const uint32_t smu = (uint32_t)__cvta_generic_to_shared(smem_raw);
    const uint32_t O_OFF = smu + (uint32_t)offsetof(SmemScan, Os);
    const uint32_t R_OFF = smu + (uint32_t)offsetof(SmemScan, Rs);
    const uint32_t S_OFF = smu + (uint32_t)offsetof(SmemScan, allStats);

    const int tid = threadIdx.x;
    const int rank = blockIdx.x;          // cluster cta rank == head
    const int b = blockIdx.y;             // batch
    const int ks = tid >> 6;              // k-slice
    const int cl = tid & 63;              // column within head
    const int col = rank * 64 + cl;       // global column
    const ulonglong2* Wp = (const ulonglong2*)g_Wpack;

    const float4* Xs4 = (const float4*)sm->Xs;
    const float4* Os4 = (const float4*)sm->Os;
    float* Xsf = (float*)sm->Xs;

    // Hoisted per-thread constants
    const float bq2 = bqkv[col];
    const float bk2 = bqkv[DD + col];
    const float bv2 = bqkv[2 * DD + col];
    const float bo2 = bo[col];
    const float4 lng0 = ((const float4*)lng)[tid & 127];
    const float4 lnb0 = ((const float4*)lnb)[tid & 127];
    const float4 lng1 = ((const float4*)lng)[(tid + 512) & 127];
    const float4 lnb1 = ((const float4*)lnb)[(tid + 512) & 127];

    // Init Xs = mem_init (M0 broadcast)
    {
        const float4* src = (const float4*)mem_init;
        float4* xd = (float4*)sm->Xs;
        xd[tid] = src[tid];
        xd[tid + 512] = src[tid + 512];
    }
    // Prime the weight ring for step 0
    STAGE_QKV(0); STAGE_QKV(1); STAGE_QKV(2);
    __syncthreads();

    for (int t = 0; t < TT; t++) {
        // --- prefetch y_t's k,v head-slice into row 8 ---------------------------
        if (tid < 32) {
            const float4* kvy = (const float4*)&g_KVy[b * TT + t][0];
            int q = tid & 15;
            if (tid < 16) {
                float4 v = kvy[rank * 16 + q];
                *(float4*)&sm->Ks2[NM][q * 4] = v;
            } else {
                float4 v = kvy[128 + rank * 16 + q];
                *(float4*)&sm->Vs2[NM][q * 4] = v;
            }
        }

        // --- phase 1: fused Q/K/V partial projections (smem-staged weights) -----
        {
            unsigned long long acc[3][NM];
#pragma unroll
            for (int p = 0; p < 3; p++)
#pragma unroll
                for (int i = 0; i < NM; i++) acc[p][i] = 0ull;

#pragma unroll
            for (int kk = 0; kk < 16; kk++) {
                if (kk <= 13)      cp_wait<2>();
                else if (kk == 14) cp_wait<1>();
                else               cp_wait<0>();
                const char* wsl = wbufc + (kk & 3) * 24576;
                ulonglong2 wq = *(const ulonglong2*)(wsl + tid * 16);
                ulonglong2 wk = *(const ulonglong2*)(wsl + 8192 + tid * 16);
                ulonglong2 wv = *(const ulonglong2*)(wsl + 16384 + tid * 16);
                const int xc = ks * 16 + kk;          // float4 chunk in row
#pragma unroll
                for (int i = 0; i < NM; i++) {
                    ulonglong2 x = *(const ulonglong2*)(Xs4 + i * 128 + xc);
                    fma2(acc[0][i], x.x, wq.x); fma2(acc[0][i], x.y, wq.y);
                    fma2(acc[1][i], x.x, wk.x); fma2(acc[1][i], x.y, wk.y);
                    fma2(acc[2][i], x.x, wv.x); fma2(acc[2][i], x.y, wv.y);
                }
                if (kk + 3 < 16) STAGE_QKV(kk + 3);
            }
            // store partials [p][i][ks][cl] (cl-contiguous -> conflict-free)
#pragma unroll
            for (int p = 0; p < 3; p++)
#pragma unroll
                for (int i = 0; i < NM; i++) {
                    float2 f = u2f2(acc[p][i]);
                    sm->part[((p * NM + i) * 8 + ks) * 64 + cl] = f.x + f.y;
                }
        }
        __syncthreads();

        // --- k-reduction: (i = tid>>6, c = tid&63), 3 outputs each ---------------
        {
            int i = ks, c = cl;
#pragma unroll
            for (int p = 0; p < 3; p++) {
                const float* pp = &sm->part[(p * NM + i) * 8 * 64 + c];
                float s = 0.f;
#pragma unroll
                for (int r2 = 0; r2 < 8; r2++) s += pp[r2 * 64];
                if (p == 0)      sm->Qs[i][c]  = s + bq2;
                else if (p == 1) sm->Ks2[i][c] = s + bk2;
                else             sm->Vs2[i][c] = s + bv2;
            }
        }
        // prime weight ring for next step (wbuf idle from here on)
        if (t + 1 < TT) { STAGE_QKV(0); STAGE_QKV(1); STAGE_QKV(2); }
        __syncthreads();

        // --- fused scores + softmax: warp i handles query row i ------------------
        {
            int w = tid >> 5, lane = tid & 31;
            if (w < NM) {
                int jj = lane < 9 ? lane : 8;
                const float* q = sm->Qs[w];
                const float* kr = sm->Ks2[jj];
                float s = 0.f;
#pragma unroll
                for (int d = 0; d < DHD; d += 4) {
                    float4 a = *(const float4*)(q + d);
                    float4 c = *(const float4*)(kr + d);
                    s = fmaf(a.x, c.x, fmaf(a.y, c.y,
                         fmaf(a.z, c.z, fmaf(a.w, c.w, s))));
                }
                s = (lane < 9) ? s * 0.125f : -1e30f;
                float mx = s;
#pragma unroll
                for (int off = 16; off; off >>= 1)
                    mx = fmaxf(mx, __shfl_xor_sync(0xffffffffu, mx, off));
                float e = expf(s - mx);
                float sum = e;
#pragma unroll
                for (int off = 16; off; off >>= 1)
                    sum += __shfl_xor_sync(0xffffffffu, sum, off);
                if (lane < 9) sm->Sc[w][lane] = e / sum;
            }
        }
        __syncthreads();

        // --- O slice = A @ V (own head), DSMEM push to all 8 CTAs ----------------
        {
            int i = ks, c = cl;
            float o = 0.f;
#pragma unroll
            for (int j = 0; j < NM + 1; j++)
                o = fmaf(sm->Sc[i][j], sm->Vs2[j][c], o);
            uint32_t off = O_OFF + (uint32_t)((i * DD + rank * 64 + c) * 4);
#pragma unroll
            for (int r = 0; r < CSIZE; r++) st_cluster_f32(off, r, o);
        }

        // --- cluster barrier #1 (O exchange); prefetch out-proj weights ----------
        ulonglong2 wo[16];
        asm volatile("barrier.cluster.arrive.aligned;" ::: "memory");
#pragma unroll
        for (int kk = 0; kk < 16; kk++)
            wo[kk] = Wp[196608 + (kk * 8 + ks) * 512 + col];
        asm volatile("barrier.cluster.wait.aligned;" ::: "memory");

        // --- out-projection partials (broadcast O reads, weights in regs) --------
        {
            unsigned long long acc[NM];
#pragma unroll
            for (int i = 0; i < NM; i++) acc[i] = 0ull;
#pragma unroll 4
            for (int kk = 0; kk < 16; kk++) {
                const int xc = ks * 16 + kk;
#pragma unroll
                for (int i = 0; i < NM; i++) {
                    ulonglong2 x = *(const ulonglong2*)(Os4 + i * 128 + xc);
                    fma2(acc[i], x.x, wo[kk].x);
                    fma2(acc[i], x.y, wo[kk].y);
                }
            }
#pragma unroll
            for (int i = 0; i < NM; i++) {
                float2 f = u2f2(acc[i]);
                sm->part[(i * 8 + ks) * 64 + cl] = f.x + f.y;
            }
        }
        __syncthreads();

        // --- reduce out-proj, residual (DSMEM push), LN partial stats ------------
        {
            int i = ks, c = cl;
            const float* pp = &sm->part[i * 8 * 64 + c];
            float s = 0.f;
#pragma unroll
            for (int r2 = 0; r2 < 8; r2++) s += pp[r2 * 64];
            float r = Xsf[i * DD + col] + s + bo2;
            uint32_t off = R_OFF + (uint32_t)((i * DD + col) * 4);
#pragma unroll
            for (int rr = 0; rr < CSIZE; rr++) st_cluster_f32(off, rr, r);

            float s1 = r, s2 = r * r;
#pragma unroll
            for (int off2 = 16; off2; off2 >>= 1) {
                s1 += __shfl_xor_sync(0xffffffffu, s1, off2);
                s2 += __shfl_xor_sync(0xffffffffu, s2, off2);
            }
            if ((tid & 31) == 0) {
                int half = (tid >> 5) & 1;
                sm->wpart[i][half][0] = s1;
                sm->wpart[i][half][1] = s2;
            }
        }
        __syncthreads();
        if (tid < NM) {
            float2 gp;
            gp.x = sm->wpart[tid][0][0] + sm->wpart[tid][1][0];
            gp.y = sm->wpart[tid][0][1] + sm->wpart[tid][1][1];
            unsigned long long pv;
            asm("mov.b64 %0, {%1,%2};" : "=l"(pv) : "f"(gp.x), "f"(gp.y));
            uint32_t off = S_OFF + (uint32_t)((rank * NM + tid) * 8);
#pragma unroll
            for (int rr = 0; rr < CSIZE; rr++) st_cluster_b64(off, rr, pv);
        }
        asm volatile("barrier.cluster.arrive.aligned;" ::: "memory");
        asm volatile("barrier.cluster.wait.aligned;" ::: "memory");   // #2

        // --- LN finalize per-warp (all data local in smem), rebuild full Xs -------
        {
            int lane = tid & 31;
            int w = tid >> 5;
            int rowA = w >> 2;          // row of v = tid
            int rowB = 4 + (w >> 2);    // row of v = tid + 512
            int lr = lane & 7;
            int row = ((lane >> 3) & 1) ? rowB : rowA;
            float2 p = *(const float2*)&sm->allStats[lr][row][0];
            float S = p.x, SS = p.y;
#pragma unroll
            for (int off = 1; off < 8; off <<= 1) {
                S  += __shfl_xor_sync(0xffffffffu, S, off);
                SS += __shfl_xor_sync(0xffffffffu, SS, off);
            }
            float mu = S * (1.f / 512.f);
            float var = SS * (1.f / 512.f) - mu * mu;
            float inv = rsqrtf(var + 1e-5f);
            float muA = __shfl_sync(0xffffffffu, mu, 0);
            float invA = __shfl_sync(0xffffffffu, inv, 0);
            float muB = __shfl_sync(0xffffffffu, mu, 8);
            float invB = __shfl_sync(0xffffffffu, inv, 8);

            const float4* rsrc = (const float4*)sm->Rs;
            float4* xd = (float4*)sm->Xs;
            {
                float4 r = rsrc[tid];
                float4 y;
                y.x = (r.x - muA) * invA * lng0.x + lnb0.x;
                y.y = (r.y - muA) * invA * lng0.y + lnb0.y;
                y.z = (r.z - muA) * invA * lng0.z + lnb0.z;
                y.w = (r.w - muA) * invA * lng0.w + lnb0.w;
                xd[tid] = y;
            }
            {
                float4 r = rsrc[tid + 512];
                float4 y;
                y.x = (r.x - muB) * invB * lng1.x + lnb1.x;
                y.y = (r.y - muB) * invB * lng1.y + lnb1.y;
                y.z = (r.z - muB) * invB * lng1.z + lnb1.z;
                y.w = (r.w - muB) * invB * lng1.w + lnb1.w;
                xd[tid + 512] = y;
            }
        }
        __syncthreads();

        // --- summary (own 64 columns); no trailing sync needed ---------------------
        if (tid < 64) {
            int c = rank * 64 + tid;
            float s = 0.f;
#pragma unroll
            for (int i = 0; i < NM; i++) s += Xsf[i * DD + c];
            g_MS[b * TT + t][c] = s * 0.125f;
        }
    }
}

// ---------------------------------------------------------------------------
// Launch
// ---------------------------------------------------------------------------
extern "C" void kernel_launch(void* const* d_in, const int* in_sizes, int n_in,
                              void* d_out, int out_size) {
    const int*   ids        = (const int*)d_in[0];
    const float* embedding  = (const float*)d_in[1];
    const float* mem_init   = (const float*)d_in[2];
    const float* in_proj_w  = (const float*)d_in[3];
    const float* in_proj_b  = (const float*)d_in[4];
    const float* out_proj_w = (const float*)d_in[5];
    const float* out_proj_b = (const float*)d_in[6];
    const float* ln_g       = (const float*)d_in[7];
    const float* ln_b       = (const float*)d_in[8];
    const float* proj_w     = (const float*)d_in[9];
    const float* proj_b     = (const float*)d_in[10];
    float* out = (float*)d_out;

    void *pKVy = nullptr, *pMS = nullptr;
    cudaGetSymbolAddress(&pKVy, g_KVy);
    cudaGetSymbolAddress(&pMS, g_MS);

    const int scan_smem = (int)sizeof(SmemScan) + WBUF_BYTES;
    cudaFuncSetAttribute(scan_kernel,
                         cudaFuncAttributeMaxDynamicSharedMemorySize, scan_smem);

    // 1) repack weights                                       (launch 0)
    repack_kernel<<<4096, 256>>>(in_proj_w, out_proj_w);

    // 2) precompute K,V projections of all tokens             (launch 1)
    {
        dim3 grid((2 * DD) / 128, (NB * TT) / 128);
        gemm_nt<true, false><<<grid, 256>>>(
            nullptr, ids, embedding,
            in_proj_w + (size_t)DD * DD, in_proj_b + DD,
            (float*)pKVy, NB * TT, 2 * DD);
    }

    // padding so ncu lands on the scan (profiled index = 3)   (launch 2)
    dummy_kernel<<<1, 32>>>();

    // 3) sequential scan: 16 clusters x 8 CTAs                (launch 3)
    scan_kernel<<<dim3(CSIZE, NB), SCAN_THREADS, scan_smem>>>(
        mem_init, in_proj_b, out_proj_b, ln_g, ln_b);

    // 4) final projection: relu(MS @ proj_w^T + proj_b)       (launch 4)
    {
        dim3 grid(OUTF / 128, (NB * TT) / 128);
        gemm_nt<false, true><<<grid, 256>>>(
            (const float*)pMS, nullptr, nullptr,
            proj_w, proj_b, out, NB * TT, OUTF);
    }
}

// round 17
// speedup vs baseline: 1.5246x; 1.1895x over previous
#include <cuda_runtime.h>
#include <cuda_bf16.h>
#include <math.h>
#include <stdint.h>
#include <stddef.h>
#include <string.h>

#define NB 16
#define TT 512
#define DD 512
#define NM 8
#define DHD 64
#define OUTF 2048
#define CSIZE 8
#define SCAN_THREADS 512

// ---------------------------------------------------------------------------
// Scratch
// ---------------------------------------------------------------------------
__device__ __align__(16) float g_Wpack[16 * 8 * 512 * 4];   // out-proj [kk][ks][col][4]
__device__ __align__(16) uint32_t g_Wm[8 * 32 * 12 * 2 * 32 * 4]; // QKV mma fragments
__device__ __align__(16) float g_KVy[NB * TT][2 * DD];
__device__ __align__(16) float g_MS[NB * TT][DD];

// ---------------------------------------------------------------------------
// helpers
// ---------------------------------------------------------------------------
__device__ __forceinline__ void fma2(unsigned long long& d,
                                     unsigned long long a, unsigned long long b) {
    asm("fma.rn.f32x2 %0, %1, %2, %0;" : "+l"(d) : "l"(a), "l"(b));
}
__device__ __forceinline__ float2 u2f2(unsigned long long v) {
    float2 f; asm("mov.b64 {%0,%1}, %2;" : "=f"(f.x), "=f"(f.y) : "l"(v)); return f;
}
__device__ __forceinline__ void st_cluster_f32(uint32_t laddr, int r, float v) {
    uint32_t pa;
    asm volatile("mapa.shared::cluster.u32 %0, %1, %2;" : "=r"(pa) : "r"(laddr), "r"(r));
    asm volatile("st.shared::cluster.f32 [%0], %1;" :: "r"(pa), "f"(v));
}
__device__ __forceinline__ void st_cluster_b64(uint32_t laddr, int r, unsigned long long v) {
    uint32_t pa;
    asm volatile("mapa.shared::cluster.u32 %0, %1, %2;" : "=r"(pa) : "r"(laddr), "r"(r));
    asm volatile("st.shared::cluster.b64 [%0], %1;" :: "r"(pa), "l"(v));
}
__device__ __forceinline__ void mma_bf16(float& d0, float& d1, float& d2, float& d3,
                                         uint32_t a0, uint32_t a1, uint32_t a2, uint32_t a3,
                                         uint32_t b0, uint32_t b1) {
    asm volatile("mma.sync.aligned.m16n8k16.row.col.f32.bf16.bf16.f32 "
        "{%0,%1,%2,%3}, {%4,%5,%6,%7}, {%8,%9}, {%0,%1,%2,%3};"
        : "+f"(d0), "+f"(d1), "+f"(d2), "+f"(d3)
        : "r"(a0), "r"(a1), "r"(a2), "r"(a3), "r"(b0), "r"(b1));
}
__device__ __forceinline__ uint32_t pkbf(float e0, float e1) {
    __nv_bfloat16 b0 = __float2bfloat16(e0), b1 = __float2bfloat16(e1);
    unsigned short u0, u1;
    memcpy(&u0, &b0, 2); memcpy(&u1, &b1, 2);
    return (uint32_t)u0 | ((uint32_t)u1 << 16);
}
__device__ __forceinline__ float bfhi(float x) {
    __nv_bfloat16 h = __float2bfloat16(x);
    return __bfloat162float(h);
}

// ---------------------------------------------------------------------------
// Repack out-proj weights (unchanged path)
// ---------------------------------------------------------------------------
__global__ void repack_kernel(const float* __restrict__ Wo) {
    int idx = blockIdx.x * 256 + threadIdx.x;       // 2^18
    int e = idx & 3, col = (idx >> 2) & 511, ks = (idx >> 11) & 7, kk = idx >> 14;
    g_Wpack[idx] = Wo[(size_t)col * 512 + ks * 64 + kk * 4 + e];
}

// ---------------------------------------------------------------------------
// Repack QKV weights into mma A-fragment order.
// bi = ((rank*32+ks2)*12+mt)*2+term, 128 thr = lane*4+reg
// a-reg (row r+ (reg&1)*8, col c + (reg&2)*4), r=lane/4, c=(lane%4)*2
// ---------------------------------------------------------------------------
__global__ void repack_mma_kernel(const float* __restrict__ Wqkv) {
    int bi = blockIdx.x;
    int term = bi & 1;
    int mt = (bi >> 1) % 12;
    int ks2 = (bi / 24) % 32;
    int rank = bi / 768;
    int lane = threadIdx.x >> 2, reg = threadIdx.x & 3;
    int r = lane >> 2, c = (lane & 3) * 2;
    int row = r + (reg & 1) * 8;
    int colk = c + (reg & 2) * 4;
    int m = mt * 16 + row;
    int k = ks2 * 16 + colk;
    int p = m >> 6;
    int wrow = p * 512 + rank * 64 + (m & 63);
    float w0 = Wqkv[(size_t)wrow * 512 + k];
    float w1 = Wqkv[(size_t)wrow * 512 + k + 1];
    uint32_t pk;
    if (term == 0) pk = pkbf(w0, w1);
    else           pk = pkbf(w0 - bfhi(w0), w1 - bfhi(w1));
    g_Wm[(size_t)bi * 128 + threadIdx.x] = pk;
}

// ---------------------------------------------------------------------------
// Generic GEMM-NT (unchanged)
// ---------------------------------------------------------------------------
template <bool GATHER, bool RELU>
__global__ __launch_bounds__(256) void gemm_nt(
    const float* __restrict__ A, const int* __restrict__ ids,
    const float* __restrict__ emb,
    const float* __restrict__ W, const float* __restrict__ bias,
    float* __restrict__ C, int M, int N)
{
    __shared__ float As[16][132];
    __shared__ float Bs[16][132];
    const int tid = threadIdx.x, ty = tid >> 4, tx = tid & 15;
    const int m0 = blockIdx.y * 128, n0 = blockIdx.x * 128;
    float acc[8][8];
#pragma unroll
    for (int i = 0; i < 8; i++)
#pragma unroll
        for (int j = 0; j < 8; j++) acc[i][j] = 0.f;
    for (int kt = 0; kt < 512; kt += 16) {
#pragma unroll
        for (int s = 0; s < 2; s++) {
            int slot = tid + s * 256, r = slot >> 2, q = (slot & 3) * 4;
            float4 v, w;
            if (GATHER) {
                int id = ids[m0 + r];
                v = (id != 0) ? *(const float4*)(emb + (size_t)id * 512 + kt + q)
                              : make_float4(0.f, 0.f, 0.f, 0.f);
            } else {
                v = *(const float4*)(A + (size_t)(m0 + r) * 512 + kt + q);
            }
            w = *(const float4*)(W + (size_t)(n0 + r) * 512 + kt + q);
            As[q + 0][r] = v.x; As[q + 1][r] = v.y; As[q + 2][r] = v.z; As[q + 3][r] = v.w;
            Bs[q + 0][r] = w.x; Bs[q + 1][r] = w.y; Bs[q + 2][r] = w.z; Bs[q + 3][r] = w.w;
        }
        __syncthreads();
#pragma unroll
        for (int kk = 0; kk < 16; kk++) {
            const float4 a0 = *(const float4*)&As[kk][ty * 8];
            const float4 a1 = *(const float4*)&As[kk][ty * 8 + 4];
            const float4 b0 = *(const float4*)&Bs[kk][tx * 8];
            const float4 b1 = *(const float4*)&Bs[kk][tx * 8 + 4];
            float ar[8] = {a0.x, a0.y, a0.z, a0.w, a1.x, a1.y, a1.z, a1.w};
            float br[8] = {b0.x, b0.y, b0.z, b0.w, b1.x, b1.y, b1.z, b1.w};
#pragma unroll
            for (int i = 0; i < 8; i++)
#pragma unroll
                for (int j = 0; j < 8; j++) acc[i][j] = fmaf(ar[i], br[j], acc[i][j]);
        }
        __syncthreads();
    }
#pragma unroll
    for (int i = 0; i < 8; i++)
#pragma unroll
        for (int j = 0; j < 8; j++) {
            float v = acc[i][j] + bias[n0 + tx * 8 + j];
            if (RELU) v = fmaxf(v, 0.f);
            C[(size_t)(m0 + ty * 8 + i) * N + n0 + tx * 8 + j] = v;
        }
}

// ---------------------------------------------------------------------------
// Scan kernel: QKV via warp-level bf16 mma (3-term split); rest as R13.
// ---------------------------------------------------------------------------
struct SmemScan {
    float Xs[NM][DD];
    float Os[NM][DD];
    float Rs[NM][DD];
    float part[NM * 8 * 64];
    float Qs[NM][68];
    float Ks2[NM + 1][68];
    float Vs2[NM + 1][68];
    float Sc[NM][12];
    float wpart[NM][2][2];
    float allStats[CSIZE][NM][2];
    float bq_s[64], bk_s[64], bv_s[64], bo_s[64];
};
#define BBUF_BYTES (32 * 32 * 16)   // [ks2][lane]{b0h,b1h,b0l,b1l}
#define SCAN_SMEM ((int)(sizeof(SmemScan) + BBUF_BYTES))

__global__ __launch_bounds__(SCAN_THREADS, 1) __cluster_dims__(CSIZE, 1, 1)
void scan_kernel(const float* __restrict__ mem_init,
                 const float* __restrict__ bqkv, const float* __restrict__ bo,
                 const float* __restrict__ lng, const float* __restrict__ lnb)
{
    extern __shared__ __align__(16) char smem_raw[];
    SmemScan* sm = (SmemScan*)smem_raw;
    uint4* Bb = (uint4*)(smem_raw + sizeof(SmemScan));
    const uint32_t smu = (uint32_t)__cvta_generic_to_shared(smem_raw);
    const uint32_t O_OFF = smu + (uint32_t)offsetof(SmemScan, Os);
    const uint32_t R_OFF = smu + (uint32_t)offsetof(SmemScan, Rs);
    const uint32_t S_OFF = smu + (uint32_t)offsetof(SmemScan, allStats);

    const int tid = threadIdx.x, wid = tid >> 5, lane = tid & 31;
    const int rank = blockIdx.x, b = blockIdx.y;
    const int ks = tid >> 6, cl = tid & 63, col = rank * 64 + cl;
    const ulonglong2* Wp = (const ulonglong2*)g_Wpack;
    const float4* Xs4 = (const float4*)sm->Xs;
    const float4* Os4 = (const float4*)sm->Os;
    float* Xsf = (float*)sm->Xs;

    const float bo2 = bo[col];
    const float4 lng0 = ((const float4*)lng)[tid & 127];
    const float4 lnb0 = ((const float4*)lnb)[tid & 127];
    const float4 lng1 = ((const float4*)lng)[(tid + 512) & 127];
    const float4 lnb1 = ((const float4*)lnb)[(tid + 512) & 127];

    if (tid < 64) {
        sm->bq_s[tid] = bqkv[rank * 64 + tid];
        sm->bk_s[tid] = bqkv[DD + rank * 64 + tid];
        sm->bv_s[tid] = bqkv[2 * DD + rank * 64 + tid];
        sm->bo_s[tid] = bo[rank * 64 + tid];
    }
    {
        const float4* src = (const float4*)mem_init;
        float4* xd = (float4*)sm->Xs;
        xd[tid] = src[tid];
        xd[tid + 512] = src[tid + 512];
    }
    __syncthreads();

    // QKV fragment base for this head
    const uint4* Wm4 = (const uint4*)g_Wm + (size_t)rank * (32 * 12 * 2 * 32);

    for (int t = 0; t < TT; t++) {
        // --- y_t k,v head-slice -> row 8 ------------------------------------
        if (tid < 32) {
            const float4* kvy = (const float4*)&g_KVy[b * TT + t][0];
            int q = tid & 15;
            if (tid < 16) *(float4*)&sm->Ks2[NM][q * 4] = kvy[rank * 16 + q];
            else          *(float4*)&sm->Vs2[NM][q * 4] = kvy[128 + rank * 16 + q];
        }
        // --- build B fragments (X -> bf16 hi/lo, mma col-major layout) -------
#pragma unroll
        for (int s = 0; s < 2; s++) {
            int it = tid + s * 512;          // 0..1023
            int ks2 = it >> 5, ln = it & 31;
            int n = ln >> 2, c = (ln & 3) * 2;
            int k0 = ks2 * 16 + c;
            float2 xa = *(const float2*)&Xsf[n * 512 + k0];
            float2 xb = *(const float2*)&Xsf[n * 512 + k0 + 8];
            uint4 v;
            v.x = pkbf(xa.x, xa.y);
            v.y = pkbf(xb.x, xb.y);
            v.z = pkbf(xa.x - bfhi(xa.x), xa.y - bfhi(xa.y));
            v.w = pkbf(xb.x - bfhi(xb.x), xb.y - bfhi(xb.y));
            Bb[it] = v;
        }
        __syncthreads();

        // --- QKV via warp mma: warp wid (<12) owns 16 output cols -----------
        if (wid < 12) {
            float d10 = 0.f, d11 = 0.f, d12 = 0.f, d13 = 0.f;
            float d20 = 0.f, d21 = 0.f, d22 = 0.f, d23 = 0.f;
            float d30 = 0.f, d31 = 0.f, d32 = 0.f, d33 = 0.f;
#pragma unroll 4
            for (int ks2 = 0; ks2 < 32; ks2++) {
                int base = ((ks2 * 12 + wid) * 2) * 32 + lane;
                uint4 wh = Wm4[base];
                uint4 wl = Wm4[base + 32];
                uint4 bb = Bb[ks2 * 32 + lane];
                mma_bf16(d10, d11, d12, d13, wh.x, wh.y, wh.z, wh.w, bb.x, bb.y);
                mma_bf16(d20, d21, d22, d23, wl.x, wl.y, wl.z, wl.w, bb.x, bb.y);
                mma_bf16(d30, d31, d32, d33, wh.x, wh.y, wh.z, wh.w, bb.z, bb.w);
            }
            float* outA = (wid < 4) ? &sm->Qs[0][0]
                        : (wid < 8) ? &sm->Ks2[0][0] : &sm->Vs2[0][0];
            const float* bA = (wid < 4) ? sm->bq_s : (wid < 8) ? sm->bk_s : sm->bv_s;
            int mloc = (wid & 3) * 16 + (lane >> 2);
            int i0 = (lane & 3) * 2;
            outA[i0 * 68 + mloc]           = d10 + d20 + d30 + bA[mloc];
            outA[(i0 + 1) * 68 + mloc]     = d11 + d21 + d31 + bA[mloc];
            outA[i0 * 68 + mloc + 8]       = d12 + d22 + d32 + bA[mloc + 8];
            outA[(i0 + 1) * 68 + mloc + 8] = d13 + d23 + d33 + bA[mloc + 8];
        }
        __syncthreads();

        // --- fused scores + softmax (warp i = query row i) --------------------
        if (wid < NM) {
            int jj = lane < 9 ? lane : 8;
            const float* q = sm->Qs[wid];
            const float* kr = sm->Ks2[jj];
            float s = 0.f;
#pragma unroll
            for (int d = 0; d < DHD; d += 4) {
                float4 a = *(const float4*)(q + d);
                float4 c = *(const float4*)(kr + d);
                s = fmaf(a.x, c.x, fmaf(a.y, c.y, fmaf(a.z, c.z, fmaf(a.w, c.w, s))));
            }
            s = (lane < 9) ? s * 0.125f : -1e30f;
            float mx = s;
#pragma unroll
            for (int off = 16; off; off >>= 1)
                mx = fmaxf(mx, __shfl_xor_sync(0xffffffffu, mx, off));
            float e = expf(s - mx), sum = e;
#pragma unroll
            for (int off = 16; off; off >>= 1)
                sum += __shfl_xor_sync(0xffffffffu, sum, off);
            if (lane < 9) sm->Sc[wid][lane] = e / sum;
        }
        __syncthreads();

        // --- O = A @ V, DSMEM push to all 8 CTAs ------------------------------
        {
            float o = 0.f;
#pragma unroll
            for (int j = 0; j < NM + 1; j++)
                o = fmaf(sm->Sc[ks][j], sm->Vs2[j][cl], o);
            uint32_t off = O_OFF + (uint32_t)((ks * DD + rank * 64 + cl) * 4);
#pragma unroll
            for (int r = 0; r < CSIZE; r++) st_cluster_f32(off, r, o);
        }

        // --- cluster barrier #1; prefetch out-proj weights --------------------
        ulonglong2 wo[16];
        asm volatile("barrier.cluster.arrive.aligned;" ::: "memory");
#pragma unroll
        for (int kk = 0; kk < 16; kk++)
            wo[kk] = Wp[(kk * 8 + ks) * 512 + col];
        asm volatile("barrier.cluster.wait.aligned;" ::: "memory");

        // --- out-projection partials ------------------------------------------
        {
            unsigned long long acc[NM];
#pragma unroll
            for (int i = 0; i < NM; i++) acc[i] = 0ull;
#pragma unroll 4
            for (int kk = 0; kk < 16; kk++) {
                const int xc = ks * 16 + kk;
#pragma unroll
                for (int i = 0; i < NM; i++) {
                    ulonglong2 x = *(const ulonglong2*)(Os4 + i * 128 + xc);
                    fma2(acc[i], x.x, wo[kk].x);
                    fma2(acc[i], x.y, wo[kk].y);
                }
            }
#pragma unroll
            for (int i = 0; i < NM; i++) {
                float2 f = u2f2(acc[i]);
                sm->part[(i * 8 + ks) * 64 + cl] = f.x + f.y;
            }
        }
        __syncthreads();

        // --- reduce out-proj, residual (DSMEM push), LN partial stats ---------
        {
            const float* pp = &sm->part[ks * 8 * 64 + cl];
            float s = 0.f;
#pragma unroll
            for (int r2 = 0; r2 < 8; r2++) s += pp[r2 * 64];
            float r = Xsf[ks * DD + col] + s + bo2;
            uint32_t off = R_OFF + (uint32_t)((ks * DD + col) * 4);
#pragma unroll
            for (int rr = 0; rr < CSIZE; rr++) st_cluster_f32(off, rr, r);

            float s1 = r, s2 = r * r;
#pragma unroll
            for (int o2 = 16; o2; o2 >>= 1) {
                s1 += __shfl_xor_sync(0xffffffffu, s1, o2);
                s2 += __shfl_xor_sync(0xffffffffu, s2, o2);
            }
            if (lane == 0) {
                sm->wpart[ks][wid & 1][0] = s1;
                sm->wpart[ks][wid & 1][1] = s2;
            }
        }
        __syncthreads();
        if (tid < NM) {
            float2 gp;
            gp.x = sm->wpart[tid][0][0] + sm->wpart[tid][1][0];
            gp.y = sm->wpart[tid][0][1] + sm->wpart[tid][1][1];
            unsigned long long pv;
            asm("mov.b64 %0, {%1,%2};" : "=l"(pv) : "f"(gp.x), "f"(gp.y));
            uint32_t off = S_OFF + (uint32_t)((rank * NM + tid) * 8);
#pragma unroll
            for (int rr = 0; rr < CSIZE; rr++) st_cluster_b64(off, rr, pv);
        }
        asm volatile("barrier.cluster.arrive.aligned;" ::: "memory");
        asm volatile("barrier.cluster.wait.aligned;" ::: "memory");   // #2

        // --- LN finalize per-warp, rebuild full Xs ------------------------------
        {
            int rowA = wid >> 2, rowB = 4 + (wid >> 2);
            int lr = lane & 7;
            int row = ((lane >> 3) & 1) ? rowB : rowA;
            float2 p = *(const float2*)&sm->allStats[lr][row][0];
            float S = p.x, SS = p.y;
#pragma unroll
            for (int off = 1; off < 8; off <<= 1) {
                S  += __shfl_xor_sync(0xffffffffu, S, off);
                SS += __shfl_xor_sync(0xffffffffu, SS, off);
            }
            float mu = S * (1.f / 512.f);
            float inv = rsqrtf(SS * (1.f / 512.f) - mu * mu + 1e-5f);
            float muA = __shfl_sync(0xffffffffu, mu, 0);
            float invA = __shfl_sync(0xffffffffu, inv, 0);
            float muB = __shfl_sync(0xffffffffu, mu, 8);
            float invB = __shfl_sync(0xffffffffu, inv, 8);
            const float4* rsrc = (const float4*)sm->Rs;
            float4* xd = (float4*)sm->Xs;
            float4 r0 = rsrc[tid], y;
            y.x = (r0.x - muA) * invA * lng0.x + lnb0.x;
            y.y = (r0.y - muA) * invA * lng0.y + lnb0.y;
            y.z = (r0.z - muA) * invA * lng0.z + lnb0.z;
            y.w = (r0.w - muA) * invA * lng0.w + lnb0.w;
            xd[tid] = y;
            float4 r1 = rsrc[tid + 512];
            y.x = (r1.x - muB) * invB * lng1.x + lnb1.x;
            y.y = (r1.y - muB) * invB * lng1.y + lnb1.y;
            y.z = (r1.z - muB) * invB * lng1.z + lnb1.z;
            y.w = (r1.w - muB) * invB * lng1.w + lnb1.w;
            xd[tid + 512] = y;
        }
        __syncthreads();

        // --- summary (own 64 columns) --------------------------------------------
        if (tid < 64) {
            int c = rank * 64 + tid;
            float s = 0.f;
#pragma unroll
            for (int i = 0; i < NM; i++) s += Xsf[i * DD + c];
            g_MS[b * TT + t][c] = s * 0.125f;
        }
        __syncthreads();
    }
}

// ---------------------------------------------------------------------------
// Launch
// ---------------------------------------------------------------------------
extern "C" void kernel_launch(void* const* d_in, const int* in_sizes, int n_in,
                              void* d_out, int out_size) {
    const int*   ids        = (const int*)d_in[0];
    const float* embedding  = (const float*)d_in[1];
    const float* mem_init   = (const float*)d_in[2];
    const float* in_proj_w  = (const float*)d_in[3];
    const float* in_proj_b  = (const float*)d_in[4];
    const float* out_proj_w = (const float*)d_in[5];
    const float* out_proj_b = (const float*)d_in[6];
    const float* ln_g       = (const float*)d_in[7];
    const float* ln_b       = (const float*)d_in[8];
    const float* proj_w     = (const float*)d_in[9];
    const float* proj_b     = (const float*)d_in[10];
    float* out = (float*)d_out;

    void *pKVy = nullptr, *pMS = nullptr;
    cudaGetSymbolAddress(&pKVy, g_KVy);
    cudaGetSymbolAddress(&pMS, g_MS);
    cudaFuncSetAttribute(scan_kernel,
                         cudaFuncAttributeMaxDynamicSharedMemorySize, SCAN_SMEM);

    repack_kernel<<<1024, 256>>>(out_proj_w);                       // launch 0
    repack_mma_kernel<<<6144, 128>>>(in_proj_w);                    // launch 1
    {
        dim3 grid((2 * DD) / 128, (NB * TT) / 128);                 // launch 2
        gemm_nt<true, false><<<grid, 256>>>(
            nullptr, ids, embedding,
            in_proj_w + (size_t)DD * DD, in_proj_b + DD,
            (float*)pKVy, NB * TT, 2 * DD);
    }
    scan_kernel<<<dim3(CSIZE, NB), SCAN_THREADS, SCAN_SMEM>>>(      // launch 3
        mem_init, in_proj_b, out_proj_b, ln_g, ln_b);
    {
        dim3 grid(OUTF / 128, (NB * TT) / 128);                     // launch 4
        gemm_nt<false, true><<<grid, 256>>>(
            (const float*)pMS, nullptr, nullptr,
            proj_w, proj_b, out, NB * TT, OUTF);
    }
}